// round 2
// baseline (speedup 1.0000x reference)
#include <cuda_runtime.h>
#include <math.h>

// Problem constants
#define Bc   8
#define Sc   1024
#define Dc   1024
#define Hc   16
#define DKc  64
#define Mrows (Bc*Sc)      // 8192

// Scratch (device globals: allocation-free)
__device__ float g_qh[Bc*Hc*Sc*DKc];   // [B,H,S,64]
__device__ float g_kh[Bc*Hc*Sc*DKc];
__device__ float g_vh[Bc*Hc*Sc*DKc];
__device__ float g_att[Bc*Sc*Hc*DKc];  // [B,S,H*64]

// ---------------------------------------------------------------------------
// Generic SGEMM: C = A (MxK) * W^T (W is NxK row-major).
// mode 0: C row-major [M,N]; mode 1: remap n=(h*64+kk), m=(b*1024+s) ->
//         C[((b*16+h)*1024+s)*64+kk]  ([B,H,S,64] layout)
// Block: 128x128 tile, BK=8, 256 threads, 8x8 per thread.
// ---------------------------------------------------------------------------
__global__ __launch_bounds__(256) void sgemm_nt(
    const float* __restrict__ A, const float* __restrict__ W,
    float* __restrict__ C, int M, int N, int K, int mode)
{
    __shared__ float As[8][132];
    __shared__ float Bs[8][132];

    int tid = threadIdx.x;
    int tx = tid & 15, ty = tid >> 4;
    int m0 = blockIdx.y * 128, n0 = blockIdx.x * 128;

    float acc[8][8];
#pragma unroll
    for (int i = 0; i < 8; i++)
#pragma unroll
        for (int j = 0; j < 8; j++) acc[i][j] = 0.f;

    int lrow = tid >> 1;           // 0..127
    int lc4  = (tid & 1) * 4;      // 0 or 4
    const float* Aptr = A + (size_t)(m0 + lrow) * K + lc4;
    const float* Wptr = W + (size_t)(n0 + lrow) * K + lc4;

    for (int k0 = 0; k0 < K; k0 += 8) {
        float4 av = *(const float4*)(Aptr + k0);
        float4 bv = *(const float4*)(Wptr + k0);
        As[lc4+0][lrow] = av.x; As[lc4+1][lrow] = av.y;
        As[lc4+2][lrow] = av.z; As[lc4+3][lrow] = av.w;
        Bs[lc4+0][lrow] = bv.x; Bs[lc4+1][lrow] = bv.y;
        Bs[lc4+2][lrow] = bv.z; Bs[lc4+3][lrow] = bv.w;
        __syncthreads();

#pragma unroll
        for (int k = 0; k < 8; k++) {
            float a[8], b[8];
            *(float4*)&a[0] = *(const float4*)&As[k][ty*8];
            *(float4*)&a[4] = *(const float4*)&As[k][ty*8+4];
            *(float4*)&b[0] = *(const float4*)&Bs[k][tx*8];
            *(float4*)&b[4] = *(const float4*)&Bs[k][tx*8+4];
#pragma unroll
            for (int i = 0; i < 8; i++)
#pragma unroll
                for (int j = 0; j < 8; j++)
                    acc[i][j] += a[i] * b[j];
        }
        __syncthreads();
    }

#pragma unroll
    for (int i = 0; i < 8; i++) {
        int m = m0 + ty*8 + i;
#pragma unroll
        for (int j = 0; j < 8; j++) {
            int n = n0 + tx*8 + j;
            float val = acc[i][j];
            if (mode == 0) {
                C[(size_t)m * N + n] = val;
            } else {
                int b = m >> 10, s = m & 1023;
                int h = n >> 6,  kk = n & 63;
                C[((((size_t)b*Hc + h) << 10) + s) * 64 + kk] = val;
            }
        }
    }
}

// ---------------------------------------------------------------------------
// Fused flash attention: per (b,h), 64-query tiles x 64-key tiles, DK=DV=64.
// Masks: keep iff (j <= i) && (j < pm1[b]) && (i < pm2[b]); else -1e10.
// Fully-masked rows reduce to uniform softmax over all S (matches reference).
// att output layout: [B, S, H*64]
// ---------------------------------------------------------------------------
#define ATT_LD 68
#define ATT_SMEM ((4*64*ATT_LD + 192) * 4)

__global__ __launch_bounds__(256) void attn_kernel(
    const float* __restrict__ qh, const float* __restrict__ kh,
    const float* __restrict__ vh, const int* __restrict__ pm1,
    const int* __restrict__ pm2, float* __restrict__ att)
{
    extern __shared__ float sm[];
    float* Qs   = sm;                   // [64][68]
    float* Ks   = Qs + 64*ATT_LD;       // [64][68]
    float* Vs   = Ks + 64*ATT_LD;       // [64][68]
    float* Ps   = Vs + 64*ATT_LD;       // [64][68]
    float* m_s  = Ps + 64*ATT_LD;       // [64]
    float* l_s  = m_s + 64;             // [64]
    float* al_s = l_s + 64;             // [64]

    int tid = threadIdx.x;
    int tx = tid & 15, ty = tid >> 4;
    int r0 = ty * 4, c0 = tx * 4;
    int bh = blockIdx.y;
    int b = bh >> 4, h = bh & 15;
    int i0 = blockIdx.x * 64;
    int p1 = pm1[b], p2 = pm2[b];

    // Load Q tile
    const float* qbase = qh + ((size_t)bh * Sc + i0) * 64;
#pragma unroll
    for (int rep = 0; rep < 4; rep++) {
        int f = tid + rep * 256;
        int i = f >> 4;
        int d4 = (f & 15) * 4;
        *(float4*)&Qs[i*ATT_LD + d4] = *(const float4*)(qbase + (size_t)i*64 + d4);
    }
    if (tid < 64) { m_s[tid] = -INFINITY; l_s[tid] = 0.f; }

    float o[4][4];
#pragma unroll
    for (int i = 0; i < 4; i++)
#pragma unroll
        for (int j = 0; j < 4; j++) o[i][j] = 0.f;

    for (int kt = 0; kt < 16; kt++) {
        int j0 = kt * 64;
        __syncthreads();   // previous iter's GEMM2 done before overwriting tiles

        const float* kbase = kh + ((size_t)bh * Sc + j0) * 64;
        const float* vbase = vh + ((size_t)bh * Sc + j0) * 64;
#pragma unroll
        for (int rep = 0; rep < 4; rep++) {
            int f = tid + rep * 256;
            int i = f >> 4;
            int d4 = (f & 15) * 4;
            *(float4*)&Ks[i*ATT_LD + d4] = *(const float4*)(kbase + (size_t)i*64 + d4);
            *(float4*)&Vs[i*ATT_LD + d4] = *(const float4*)(vbase + (size_t)i*64 + d4);
        }
        __syncthreads();

        // --- GEMM1: S = Q K^T (4x4 per thread) ---
        float s[4][4];
#pragma unroll
        for (int i = 0; i < 4; i++)
#pragma unroll
            for (int j = 0; j < 4; j++) s[i][j] = 0.f;

#pragma unroll
        for (int d = 0; d < 64; d += 4) {
            float kr[4][4];
#pragma unroll
            for (int jj = 0; jj < 4; jj++) {
                float4 t = *(const float4*)&Ks[(c0+jj)*ATT_LD + d];
                kr[jj][0] = t.x; kr[jj][1] = t.y; kr[jj][2] = t.z; kr[jj][3] = t.w;
            }
#pragma unroll
            for (int ii = 0; ii < 4; ii++) {
                float4 q4 = *(const float4*)&Qs[(r0+ii)*ATT_LD + d];
#pragma unroll
                for (int jj = 0; jj < 4; jj++)
                    s[ii][jj] += q4.x*kr[jj][0] + q4.y*kr[jj][1]
                               + q4.z*kr[jj][2] + q4.w*kr[jj][3];
            }
        }

        // --- mask + scale, store to Ps ---
#pragma unroll
        for (int ii = 0; ii < 4; ii++) {
            int gi = i0 + r0 + ii;
#pragma unroll
            for (int jj = 0; jj < 4; jj++) {
                int gj = j0 + c0 + jj;
                bool keep = (gj <= gi) && (gj < p1) && (gi < p2);
                Ps[(r0+ii)*ATT_LD + c0+jj] = keep ? s[ii][jj] * 0.125f : -1e10f;
            }
        }
        __syncthreads();

        // --- online softmax update: 4 threads per row ---
        {
            int r  = tid >> 2;
            int cc = (tid & 3) * 16;
            float mx = -INFINITY;
#pragma unroll
            for (int c = 0; c < 16; c++) mx = fmaxf(mx, Ps[r*ATT_LD + cc + c]);
            mx = fmaxf(mx, __shfl_xor_sync(0xffffffffu, mx, 1));
            mx = fmaxf(mx, __shfl_xor_sync(0xffffffffu, mx, 2));
            float m_old = m_s[r];
            float m_new = fmaxf(m_old, mx);
            float sum = 0.f;
#pragma unroll
            for (int c = 0; c < 16; c++) {
                float p = __expf(Ps[r*ATT_LD + cc + c] - m_new);
                Ps[r*ATT_LD + cc + c] = p;
                sum += p;
            }
            sum += __shfl_xor_sync(0xffffffffu, sum, 1);
            sum += __shfl_xor_sync(0xffffffffu, sum, 2);
            if ((tid & 3) == 0) {
                float alpha = __expf(m_old - m_new);
                m_s[r]  = m_new;
                l_s[r]  = l_s[r] * alpha + sum;
                al_s[r] = alpha;
            }
        }
        __syncthreads();

        // --- rescale O and GEMM2: O += P V ---
#pragma unroll
        for (int ii = 0; ii < 4; ii++) {
            float a = al_s[r0 + ii];
#pragma unroll
            for (int jj = 0; jj < 4; jj++) o[ii][jj] *= a;
        }
#pragma unroll
        for (int c = 0; c < 64; c += 4) {
            float vr[4][4];
#pragma unroll
            for (int cc = 0; cc < 4; cc++) {
                float4 t = *(const float4*)&Vs[(c+cc)*ATT_LD + c0];
                vr[cc][0] = t.x; vr[cc][1] = t.y; vr[cc][2] = t.z; vr[cc][3] = t.w;
            }
#pragma unroll
            for (int ii = 0; ii < 4; ii++) {
                float4 p4 = *(const float4*)&Ps[(r0+ii)*ATT_LD + c];
#pragma unroll
                for (int jj = 0; jj < 4; jj++)
                    o[ii][jj] += p4.x*vr[0][jj] + p4.y*vr[1][jj]
                               + p4.z*vr[2][jj] + p4.w*vr[3][jj];
            }
        }
    }

    // --- epilogue: divide by l, write [B,S,H*64] ---
#pragma unroll
    for (int ii = 0; ii < 4; ii++) {
        int gi = i0 + r0 + ii;
        float inv = 1.0f / l_s[r0 + ii];
#pragma unroll
        for (int jj = 0; jj < 4; jj++)
            att[((size_t)b * Sc + gi) * (Hc*64) + h*64 + c0 + jj] = o[ii][jj] * inv;
    }
}

// ---------------------------------------------------------------------------
extern "C" void kernel_launch(void* const* d_in, const int* in_sizes, int n_in,
                              void* d_out, int out_size)
{
    const float* q   = (const float*)d_in[0];
    const float* k   = (const float*)d_in[1];
    const float* v   = (const float*)d_in[2];
    const int*   pm1 = (const int*)d_in[3];
    const int*   pm2 = (const int*)d_in[4];
    const float* Wq  = (const float*)d_in[5];
    const float* Wk  = (const float*)d_in[6];
    const float* Wv  = (const float*)d_in[7];
    const float* Wo  = (const float*)d_in[8];
    float* out = (float*)d_out;

    float *qh, *kh, *vh, *att;
    cudaGetSymbolAddress((void**)&qh,  g_qh);
    cudaGetSymbolAddress((void**)&kh,  g_kh);
    cudaGetSymbolAddress((void**)&vh,  g_vh);
    cudaGetSymbolAddress((void**)&att, g_att);

    cudaFuncSetAttribute(attn_kernel,
        cudaFuncAttributeMaxDynamicSharedMemorySize, ATT_SMEM);

    dim3 gg(Dc / 128, Mrows / 128);   // (8, 64)

    // Projections: out layout [B,H,S,64]
    sgemm_nt<<<gg, 256>>>(q, Wq, qh, Mrows, Hc*DKc, Dc, 1);
    sgemm_nt<<<gg, 256>>>(k, Wk, kh, Mrows, Hc*DKc, Dc, 1);
    sgemm_nt<<<gg, 256>>>(v, Wv, vh, Mrows, Hc*DKc, Dc, 1);

    // Fused attention
    attn_kernel<<<dim3(Sc/64, Bc*Hc), 256, ATT_SMEM>>>(qh, kh, vh, pm1, pm2, att);

    // Output projection: out = att @ Wo^T
    sgemm_nt<<<gg, 256>>>(att, Wo, out, Mrows, Dc, Dc, 0);
}

// round 4
// speedup vs baseline: 1.5308x; 1.5308x over previous
#include <cuda_runtime.h>
#include <cuda_bf16.h>
#include <math.h>
#include <stdint.h>

// Problem constants
#define Bc   8
#define Sc   1024
#define Dc   1024
#define Hc   16
#define Mrows (Bc*Sc)      // 8192
#define KTOT 3072          // split-K: A'=[hi|hi|lo], W'=[hi|lo|hi]
#define NSTG 48            // KTOT / 64

// ---------------- scratch (device globals: allocation-free) ----------------
__device__ float g_qh[Bc*Hc*Sc*64];   // [B,H,S,64]
__device__ float g_kh[Bc*Hc*Sc*64];
__device__ float g_vh[Bc*Hc*Sc*64];
__device__ float g_att[Bc*Sc*Hc*64];  // [B,S,H*64]
__device__ __nv_bfloat16 g_ap[(size_t)Mrows*KTOT];
__device__ __nv_bfloat16 g_wp[(size_t)Dc*KTOT];

__device__ __forceinline__ uint32_t smem_u32(const void* p) {
    uint32_t a;
    asm("{ .reg .u64 t; cvta.to.shared.u64 t, %1; cvt.u32.u64 %0, t; }"
        : "=r"(a) : "l"(p));
    return a;
}

// ---------------------------------------------------------------------------
// fp32 -> bf16 split conversion.  Y row = 3072 bf16:
//   hi at [c], hi-dup at [off_dup + c], lo at [off_lo + c]
// ---------------------------------------------------------------------------
__global__ __launch_bounds__(256) void conv_split(
    const float* __restrict__ X, __nv_bfloat16* __restrict__ Y,
    int total4, int off_dup, int off_lo)
{
    int i = blockIdx.x * 256 + threadIdx.x;
    if (i >= total4) return;
    int r = i >> 8;
    int c4 = (i & 255) << 2;
    float4 x = *(const float4*)(X + (size_t)r * 1024 + c4);

    __nv_bfloat16 h0 = __float2bfloat16(x.x), h1 = __float2bfloat16(x.y);
    __nv_bfloat16 h2 = __float2bfloat16(x.z), h3 = __float2bfloat16(x.w);
    __nv_bfloat16 l0 = __float2bfloat16(x.x - __bfloat162float(h0));
    __nv_bfloat16 l1 = __float2bfloat16(x.y - __bfloat162float(h1));
    __nv_bfloat16 l2 = __float2bfloat16(x.z - __bfloat162float(h2));
    __nv_bfloat16 l3 = __float2bfloat16(x.w - __bfloat162float(h3));

    uint32_t hA = (uint32_t)__bfloat16_as_ushort(h0) | ((uint32_t)__bfloat16_as_ushort(h1) << 16);
    uint32_t hB = (uint32_t)__bfloat16_as_ushort(h2) | ((uint32_t)__bfloat16_as_ushort(h3) << 16);
    uint32_t lA = (uint32_t)__bfloat16_as_ushort(l0) | ((uint32_t)__bfloat16_as_ushort(l1) << 16);
    uint32_t lB = (uint32_t)__bfloat16_as_ushort(l2) | ((uint32_t)__bfloat16_as_ushort(l3) << 16);

    size_t base = (size_t)r * KTOT;
    *(uint2*)(Y + base + c4)           = make_uint2(hA, hB);
    *(uint2*)(Y + base + off_dup + c4) = make_uint2(hA, hB);
    *(uint2*)(Y + base + off_lo + c4)  = make_uint2(lA, lB);
}

// ---------------------------------------------------------------------------
// bf16 mma.sync GEMM: C[8192,1024] = Ap[8192,3072] * Wp[1024,3072]^T
// CTA 128x128x64, 3-stage cp.async, 256 threads (8 warps, 2x4),
// warp tile 64x32, m16n8k16 HMMA.
// mode 0: C row-major [M,1024]; mode 1: remap to [B,H,S,64]
// ---------------------------------------------------------------------------
#define SLOT_BYTES 32768           // A 16KB + B 16KB per stage
#define GEMM_SMEM (3 * SLOT_BYTES) // 96KB

__device__ __forceinline__ void load_stage_mma(
    const __nv_bfloat16* __restrict__ Ap, const __nv_bfloat16* __restrict__ Wp,
    uint32_t abase, uint32_t bbase, int m0, int n0, int t, int tid)
{
#pragma unroll
    for (int i = 0; i < 4; i++) {
        int f = i * 256 + tid;
        int r = f >> 3, cx = f & 7;
        uint32_t sw = r * 128 + ((cx ^ (r & 7)) << 4);
        const void* ga = Ap + (size_t)(m0 + r) * KTOT + t * 64 + cx * 8;
        asm volatile("cp.async.cg.shared.global [%0], [%1], 16;" :: "r"(abase + sw), "l"(ga));
        const void* gb = Wp + (size_t)(n0 + r) * KTOT + t * 64 + cx * 8;
        asm volatile("cp.async.cg.shared.global [%0], [%1], 16;" :: "r"(bbase + sw), "l"(gb));
    }
}

__global__ __launch_bounds__(256, 2)
void gemm_mma(const __nv_bfloat16* __restrict__ Ap, const __nv_bfloat16* __restrict__ Wp,
              float* __restrict__ C, int mode)
{
    extern __shared__ __align__(128) char smem[];
    uint32_t sb = smem_u32(smem);
    int tid = threadIdx.x;
    int wid = tid >> 5, lane = tid & 31;
    int warp_m = wid >> 2, warp_n = wid & 3;      // 2 x 4
    int m0 = blockIdx.y * 128, n0 = blockIdx.x * 128;

    float acc[4][4][4];
#pragma unroll
    for (int i = 0; i < 4; i++)
#pragma unroll
        for (int j = 0; j < 4; j++)
#pragma unroll
            for (int r = 0; r < 4; r++) acc[i][j][r] = 0.f;

    // prologue: stages 0,1
    load_stage_mma(Ap, Wp, sb, sb + 16384, m0, n0, 0, tid);
    asm volatile("cp.async.commit_group;" ::: "memory");
    load_stage_mma(Ap, Wp, sb + SLOT_BYTES, sb + SLOT_BYTES + 16384, m0, n0, 1, tid);
    asm volatile("cp.async.commit_group;" ::: "memory");

    int lm15 = lane & 15, l4 = lane >> 4;

    for (int s = 0; s < NSTG; s++) {
        asm volatile("cp.async.wait_group 1;" ::: "memory");
        __syncthreads();

        // prefetch stage s+2
        if (s + 2 < NSTG) {
            uint32_t ab = sb + ((s + 2) % 3) * SLOT_BYTES;
            load_stage_mma(Ap, Wp, ab, ab + 16384, m0, n0, s + 2, tid);
        }
        asm volatile("cp.async.commit_group;" ::: "memory");

        uint32_t As = sb + (s % 3) * SLOT_BYTES;
        uint32_t Bs = As + 16384;

#pragma unroll
        for (int kk = 0; kk < 4; kk++) {
            int c0 = 2 * kk + l4;
            uint32_t a[4][4], b[2][4];
#pragma unroll
            for (int i = 0; i < 4; i++) {
                int r = warp_m * 64 + i * 16 + lm15;
                uint32_t addr = As + r * 128 + ((c0 ^ (r & 7)) << 4);
                asm volatile("ldmatrix.sync.aligned.m8n8.x4.shared.b16 {%0,%1,%2,%3}, [%4];"
                    : "=r"(a[i][0]), "=r"(a[i][1]), "=r"(a[i][2]), "=r"(a[i][3]) : "r"(addr));
            }
#pragma unroll
            for (int g = 0; g < 2; g++) {
                int r = warp_n * 32 + g * 16 + lm15;
                uint32_t addr = Bs + r * 128 + ((c0 ^ (r & 7)) << 4);
                asm volatile("ldmatrix.sync.aligned.m8n8.x4.shared.b16 {%0,%1,%2,%3}, [%4];"
                    : "=r"(b[g][0]), "=r"(b[g][1]), "=r"(b[g][2]), "=r"(b[g][3]) : "r"(addr));
            }
#pragma unroll
            for (int i = 0; i < 4; i++) {
#pragma unroll
                for (int j = 0; j < 4; j++) {
                    uint32_t b0 = b[j >> 1][j & 1];
                    uint32_t b1 = b[j >> 1][(j & 1) + 2];
                    asm volatile(
                        "mma.sync.aligned.m16n8k16.row.col.f32.bf16.bf16.f32 "
                        "{%0,%1,%2,%3}, {%4,%5,%6,%7}, {%8,%9}, {%0,%1,%2,%3};"
                        : "+f"(acc[i][j][0]), "+f"(acc[i][j][1]),
                          "+f"(acc[i][j][2]), "+f"(acc[i][j][3])
                        : "r"(a[i][0]), "r"(a[i][1]), "r"(a[i][2]), "r"(a[i][3]),
                          "r"(b0), "r"(b1));
                }
            }
        }
    }

    // epilogue: c frag lane mapping: rows lane/4 and lane/4+8, cols (lane%4)*2
    int lr = lane >> 2, lc = (lane & 3) * 2;
#pragma unroll
    for (int i = 0; i < 4; i++) {
#pragma unroll
        for (int j = 0; j < 4; j++) {
            int mA = m0 + warp_m * 64 + i * 16 + lr;
            int n  = n0 + warp_n * 32 + j * 8 + lc;
            if (mode == 0) {
                *(float2*)(C + (size_t)mA * 1024 + n) = make_float2(acc[i][j][0], acc[i][j][1]);
                *(float2*)(C + (size_t)(mA + 8) * 1024 + n) = make_float2(acc[i][j][2], acc[i][j][3]);
            } else {
                int h = n >> 6, kk2 = n & 63;
                int bA = mA >> 10, sA = mA & 1023;
                float* d0 = C + ((((size_t)bA * Hc + h) << 10) + sA) * 64 + kk2;
                *(float2*)d0 = make_float2(acc[i][j][0], acc[i][j][1]);
                float* d1 = C + ((((size_t)bA * Hc + h) << 10) + sA + 8) * 64 + kk2;
                *(float2*)d1 = make_float2(acc[i][j][2], acc[i][j][3]);
            }
        }
    }
}

// ---------------------------------------------------------------------------
// Fused flash attention (unchanged from passing R2 kernel)
// ---------------------------------------------------------------------------
#define ATT_LD 68
#define ATT_SMEM ((4*64*ATT_LD + 192) * 4)

__global__ __launch_bounds__(256) void attn_kernel(
    const float* __restrict__ qh, const float* __restrict__ kh,
    const float* __restrict__ vh, const int* __restrict__ pm1,
    const int* __restrict__ pm2, float* __restrict__ att)
{
    extern __shared__ float sm[];
    float* Qs   = sm;
    float* Ks   = Qs + 64*ATT_LD;
    float* Vs   = Ks + 64*ATT_LD;
    float* Ps   = Vs + 64*ATT_LD;
    float* m_s  = Ps + 64*ATT_LD;
    float* l_s  = m_s + 64;
    float* al_s = l_s + 64;

    int tid = threadIdx.x;
    int tx = tid & 15, ty = tid >> 4;
    int r0 = ty * 4, c0 = tx * 4;
    int bh = blockIdx.y;
    int b = bh >> 4, h = bh & 15;
    int i0 = blockIdx.x * 64;
    int p1 = pm1[b], p2 = pm2[b];

    const float* qbase = qh + ((size_t)bh * Sc + i0) * 64;
#pragma unroll
    for (int rep = 0; rep < 4; rep++) {
        int f = tid + rep * 256;
        int i = f >> 4;
        int d4 = (f & 15) * 4;
        *(float4*)&Qs[i*ATT_LD + d4] = *(const float4*)(qbase + (size_t)i*64 + d4);
    }
    if (tid < 64) { m_s[tid] = -INFINITY; l_s[tid] = 0.f; }

    float o[4][4];
#pragma unroll
    for (int i = 0; i < 4; i++)
#pragma unroll
        for (int j = 0; j < 4; j++) o[i][j] = 0.f;

    for (int kt = 0; kt < 16; kt++) {
        int j0 = kt * 64;
        __syncthreads();

        const float* kbase = kh + ((size_t)bh * Sc + j0) * 64;
        const float* vbase = vh + ((size_t)bh * Sc + j0) * 64;
#pragma unroll
        for (int rep = 0; rep < 4; rep++) {
            int f = tid + rep * 256;
            int i = f >> 4;
            int d4 = (f & 15) * 4;
            *(float4*)&Ks[i*ATT_LD + d4] = *(const float4*)(kbase + (size_t)i*64 + d4);
            *(float4*)&Vs[i*ATT_LD + d4] = *(const float4*)(vbase + (size_t)i*64 + d4);
        }
        __syncthreads();

        float s[4][4];
#pragma unroll
        for (int i = 0; i < 4; i++)
#pragma unroll
            for (int j = 0; j < 4; j++) s[i][j] = 0.f;

#pragma unroll
        for (int d = 0; d < 64; d += 4) {
            float kr[4][4];
#pragma unroll
            for (int jj = 0; jj < 4; jj++) {
                float4 t = *(const float4*)&Ks[(c0+jj)*ATT_LD + d];
                kr[jj][0] = t.x; kr[jj][1] = t.y; kr[jj][2] = t.z; kr[jj][3] = t.w;
            }
#pragma unroll
            for (int ii = 0; ii < 4; ii++) {
                float4 q4 = *(const float4*)&Qs[(r0+ii)*ATT_LD + d];
#pragma unroll
                for (int jj = 0; jj < 4; jj++)
                    s[ii][jj] += q4.x*kr[jj][0] + q4.y*kr[jj][1]
                               + q4.z*kr[jj][2] + q4.w*kr[jj][3];
            }
        }

#pragma unroll
        for (int ii = 0; ii < 4; ii++) {
            int gi = i0 + r0 + ii;
#pragma unroll
            for (int jj = 0; jj < 4; jj++) {
                int gj = j0 + c0 + jj;
                bool keep = (gj <= gi) && (gj < p1) && (gi < p2);
                Ps[(r0+ii)*ATT_LD + c0+jj] = keep ? s[ii][jj] * 0.125f : -1e10f;
            }
        }
        __syncthreads();

        {
            int r  = tid >> 2;
            int cc = (tid & 3) * 16;
            float mx = -INFINITY;
#pragma unroll
            for (int c = 0; c < 16; c++) mx = fmaxf(mx, Ps[r*ATT_LD + cc + c]);
            mx = fmaxf(mx, __shfl_xor_sync(0xffffffffu, mx, 1));
            mx = fmaxf(mx, __shfl_xor_sync(0xffffffffu, mx, 2));
            float m_old = m_s[r];
            float m_new = fmaxf(m_old, mx);
            float sum = 0.f;
#pragma unroll
            for (int c = 0; c < 16; c++) {
                float p = __expf(Ps[r*ATT_LD + cc + c] - m_new);
                Ps[r*ATT_LD + cc + c] = p;
                sum += p;
            }
            sum += __shfl_xor_sync(0xffffffffu, sum, 1);
            sum += __shfl_xor_sync(0xffffffffu, sum, 2);
            if ((tid & 3) == 0) {
                float alpha = __expf(m_old - m_new);
                m_s[r]  = m_new;
                l_s[r]  = l_s[r] * alpha + sum;
                al_s[r] = alpha;
            }
        }
        __syncthreads();

#pragma unroll
        for (int ii = 0; ii < 4; ii++) {
            float a = al_s[r0 + ii];
#pragma unroll
            for (int jj = 0; jj < 4; jj++) o[ii][jj] *= a;
        }
#pragma unroll
        for (int c = 0; c < 64; c += 4) {
            float vr[4][4];
#pragma unroll
            for (int cc = 0; cc < 4; cc++) {
                float4 t = *(const float4*)&Vs[(c+cc)*ATT_LD + c0];
                vr[cc][0] = t.x; vr[cc][1] = t.y; vr[cc][2] = t.z; vr[cc][3] = t.w;
            }
#pragma unroll
            for (int ii = 0; ii < 4; ii++) {
                float4 p4 = *(const float4*)&Ps[(r0+ii)*ATT_LD + c];
#pragma unroll
                for (int jj = 0; jj < 4; jj++)
                    o[ii][jj] += p4.x*vr[0][jj] + p4.y*vr[1][jj]
                               + p4.z*vr[2][jj] + p4.w*vr[3][jj];
            }
        }
    }

#pragma unroll
    for (int ii = 0; ii < 4; ii++) {
        int gi = i0 + r0 + ii;
        float inv = 1.0f / l_s[r0 + ii];
#pragma unroll
        for (int jj = 0; jj < 4; jj++)
            att[((size_t)b * Sc + gi) * (Hc*64) + h*64 + c0 + jj] = o[ii][jj] * inv;
    }
}

// ---------------------------------------------------------------------------
extern "C" void kernel_launch(void* const* d_in, const int* in_sizes, int n_in,
                              void* d_out, int out_size)
{
    const float* q   = (const float*)d_in[0];
    const float* k   = (const float*)d_in[1];
    const float* v   = (const float*)d_in[2];
    const int*   pm1 = (const int*)d_in[3];
    const int*   pm2 = (const int*)d_in[4];
    const float* Wq  = (const float*)d_in[5];
    const float* Wk  = (const float*)d_in[6];
    const float* Wv  = (const float*)d_in[7];
    const float* Wo  = (const float*)d_in[8];
    float* out = (float*)d_out;

    float *qh, *kh, *vh, *att;
    __nv_bfloat16 *ap, *wp;
    cudaGetSymbolAddress((void**)&qh,  g_qh);
    cudaGetSymbolAddress((void**)&kh,  g_kh);
    cudaGetSymbolAddress((void**)&vh,  g_vh);
    cudaGetSymbolAddress((void**)&att, g_att);
    cudaGetSymbolAddress((void**)&ap,  g_ap);
    cudaGetSymbolAddress((void**)&wp,  g_wp);

    cudaFuncSetAttribute(attn_kernel,
        cudaFuncAttributeMaxDynamicSharedMemorySize, ATT_SMEM);
    cudaFuncSetAttribute(gemm_mma,
        cudaFuncAttributeMaxDynamicSharedMemorySize, GEMM_SMEM);

    const int A4 = Mrows * 256;
    const int W4 = Dc * 256;
    dim3 gg(Dc / 128, Mrows / 128);   // (8, 64)

    // A split: [hi | hi | lo] -> off_dup=1024, off_lo=2048
    // W split: [hi | lo | hi] -> off_dup=2048, off_lo=1024
    conv_split<<<(W4 + 255) / 256, 256>>>(Wq, wp, W4, 2048, 1024);
    conv_split<<<(A4 + 255) / 256, 256>>>(q, ap, A4, 1024, 2048);
    gemm_mma<<<gg, 256, GEMM_SMEM>>>(ap, wp, qh, 1);

    conv_split<<<(W4 + 255) / 256, 256>>>(Wk, wp, W4, 2048, 1024);
    conv_split<<<(A4 + 255) / 256, 256>>>(k, ap, A4, 1024, 2048);
    gemm_mma<<<gg, 256, GEMM_SMEM>>>(ap, wp, kh, 1);

    conv_split<<<(W4 + 255) / 256, 256>>>(Wv, wp, W4, 2048, 1024);
    conv_split<<<(A4 + 255) / 256, 256>>>(v, ap, A4, 1024, 2048);
    gemm_mma<<<gg, 256, GEMM_SMEM>>>(ap, wp, vh, 1);

    attn_kernel<<<dim3(Sc/64, Bc*Hc), 256, ATT_SMEM>>>(qh, kh, vh, pm1, pm2, att);

    conv_split<<<(W4 + 255) / 256, 256>>>(Wo, wp, W4, 2048, 1024);
    conv_split<<<(A4 + 255) / 256, 256>>>(att, ap, A4, 1024, 2048);
    gemm_mma<<<gg, 256, GEMM_SMEM>>>(ap, wp, out, 0);
}

// round 5
// speedup vs baseline: 2.9241x; 1.9102x over previous
#include <cuda_runtime.h>
#include <cuda_bf16.h>
#include <math.h>
#include <stdint.h>

// Problem constants
#define Bc   8
#define Sc   1024
#define Dc   1024
#define Hc   16
#define Mrows (Bc*Sc)      // 8192
#define KTOT 3072          // split-K: A'=[hi|hi|lo], W'=[hi|lo|hi]
#define NSTG 48            // KTOT / 64

// ---------------- scratch (device globals: allocation-free) ----------------
// q/k/v split-head bf16 arrays [B,H,S,128] ([hi(64)|lo(64)]) stored in these:
__device__ __nv_bfloat16 g_qs[(size_t)Bc*Hc*Sc*128];
__device__ __nv_bfloat16 g_ks[(size_t)Bc*Hc*Sc*128];
__device__ __nv_bfloat16 g_vs[(size_t)Bc*Hc*Sc*128];
__device__ __nv_bfloat16 g_ap[(size_t)Mrows*KTOT];
__device__ __nv_bfloat16 g_wp[(size_t)Dc*KTOT];

__device__ __forceinline__ uint32_t smem_u32(const void* p) {
    uint32_t a;
    asm("{ .reg .u64 t; cvta.to.shared.u64 t, %1; cvt.u32.u64 %0, t; }"
        : "=r"(a) : "l"(p));
    return a;
}

__device__ __forceinline__ uint32_t pack_bf2(float a, float b) {
    __nv_bfloat16 ha = __float2bfloat16(a), hb = __float2bfloat16(b);
    return (uint32_t)__bfloat16_as_ushort(ha) | ((uint32_t)__bfloat16_as_ushort(hb) << 16);
}

// ---------------------------------------------------------------------------
// fp32 -> bf16 split conversion.  Y row = 3072 bf16:
//   hi at [c], hi-dup at [off_dup + c], lo at [off_lo + c]
// ---------------------------------------------------------------------------
__global__ __launch_bounds__(256) void conv_split(
    const float* __restrict__ X, __nv_bfloat16* __restrict__ Y,
    int total4, int off_dup, int off_lo)
{
    int i = blockIdx.x * 256 + threadIdx.x;
    if (i >= total4) return;
    int r = i >> 8;
    int c4 = (i & 255) << 2;
    float4 x = *(const float4*)(X + (size_t)r * 1024 + c4);

    __nv_bfloat16 h0 = __float2bfloat16(x.x), h1 = __float2bfloat16(x.y);
    __nv_bfloat16 h2 = __float2bfloat16(x.z), h3 = __float2bfloat16(x.w);
    float l0f = x.x - __bfloat162float(h0), l1f = x.y - __bfloat162float(h1);
    float l2f = x.z - __bfloat162float(h2), l3f = x.w - __bfloat162float(h3);

    uint32_t hA = (uint32_t)__bfloat16_as_ushort(h0) | ((uint32_t)__bfloat16_as_ushort(h1) << 16);
    uint32_t hB = (uint32_t)__bfloat16_as_ushort(h2) | ((uint32_t)__bfloat16_as_ushort(h3) << 16);
    uint32_t lA = pack_bf2(l0f, l1f);
    uint32_t lB = pack_bf2(l2f, l3f);

    size_t base = (size_t)r * KTOT;
    *(uint2*)(Y + base + c4)           = make_uint2(hA, hB);
    *(uint2*)(Y + base + off_dup + c4) = make_uint2(hA, hB);
    *(uint2*)(Y + base + off_lo + c4)  = make_uint2(lA, lB);
}

// ---------------------------------------------------------------------------
// bf16 mma.sync GEMM: C = Ap[8192,3072] * Wp[1024,3072]^T
// CTA 128x128x64, 3-stage cp.async, 256 threads, warp tile 64x32, m16n8k16.
// mode 0: C fp32 row-major [M,1024]
// mode 2: C bf16 split-head: out[b,h][s][kk]=hi, [s][64+kk]=lo  ([B,H,S,128])
// ---------------------------------------------------------------------------
#define SLOT_BYTES 32768
#define GEMM_SMEM (3 * SLOT_BYTES)

__device__ __forceinline__ void load_stage_mma(
    const __nv_bfloat16* __restrict__ Ap, const __nv_bfloat16* __restrict__ Wp,
    uint32_t abase, uint32_t bbase, int m0, int n0, int t, int tid)
{
#pragma unroll
    for (int i = 0; i < 4; i++) {
        int f = i * 256 + tid;
        int r = f >> 3, cx = f & 7;
        uint32_t sw = r * 128 + ((cx ^ (r & 7)) << 4);
        const void* ga = Ap + (size_t)(m0 + r) * KTOT + t * 64 + cx * 8;
        asm volatile("cp.async.cg.shared.global [%0], [%1], 16;" :: "r"(abase + sw), "l"(ga));
        const void* gb = Wp + (size_t)(n0 + r) * KTOT + t * 64 + cx * 8;
        asm volatile("cp.async.cg.shared.global [%0], [%1], 16;" :: "r"(bbase + sw), "l"(gb));
    }
}

__global__ __launch_bounds__(256, 2)
void gemm_mma(const __nv_bfloat16* __restrict__ Ap, const __nv_bfloat16* __restrict__ Wp,
              void* __restrict__ Cv, int mode)
{
    extern __shared__ __align__(128) char smem[];
    uint32_t sb = smem_u32(smem);
    int tid = threadIdx.x;
    int wid = tid >> 5, lane = tid & 31;
    int warp_m = wid >> 2, warp_n = wid & 3;
    int m0 = blockIdx.y * 128, n0 = blockIdx.x * 128;

    float acc[4][4][4];
#pragma unroll
    for (int i = 0; i < 4; i++)
#pragma unroll
        for (int j = 0; j < 4; j++)
#pragma unroll
            for (int r = 0; r < 4; r++) acc[i][j][r] = 0.f;

    load_stage_mma(Ap, Wp, sb, sb + 16384, m0, n0, 0, tid);
    asm volatile("cp.async.commit_group;" ::: "memory");
    load_stage_mma(Ap, Wp, sb + SLOT_BYTES, sb + SLOT_BYTES + 16384, m0, n0, 1, tid);
    asm volatile("cp.async.commit_group;" ::: "memory");

    int lm15 = lane & 15, l4 = lane >> 4;

    for (int s = 0; s < NSTG; s++) {
        asm volatile("cp.async.wait_group 1;" ::: "memory");
        __syncthreads();

        if (s + 2 < NSTG) {
            uint32_t ab = sb + ((s + 2) % 3) * SLOT_BYTES;
            load_stage_mma(Ap, Wp, ab, ab + 16384, m0, n0, s + 2, tid);
        }
        asm volatile("cp.async.commit_group;" ::: "memory");

        uint32_t As = sb + (s % 3) * SLOT_BYTES;
        uint32_t Bs = As + 16384;

#pragma unroll
        for (int kk = 0; kk < 4; kk++) {
            int c0 = 2 * kk + l4;
            uint32_t a[4][4], b[2][4];
#pragma unroll
            for (int i = 0; i < 4; i++) {
                int r = warp_m * 64 + i * 16 + lm15;
                uint32_t addr = As + r * 128 + ((c0 ^ (r & 7)) << 4);
                asm volatile("ldmatrix.sync.aligned.m8n8.x4.shared.b16 {%0,%1,%2,%3}, [%4];"
                    : "=r"(a[i][0]), "=r"(a[i][1]), "=r"(a[i][2]), "=r"(a[i][3]) : "r"(addr));
            }
#pragma unroll
            for (int g = 0; g < 2; g++) {
                int r = warp_n * 32 + g * 16 + lm15;
                uint32_t addr = Bs + r * 128 + ((c0 ^ (r & 7)) << 4);
                asm volatile("ldmatrix.sync.aligned.m8n8.x4.shared.b16 {%0,%1,%2,%3}, [%4];"
                    : "=r"(b[g][0]), "=r"(b[g][1]), "=r"(b[g][2]), "=r"(b[g][3]) : "r"(addr));
            }
#pragma unroll
            for (int i = 0; i < 4; i++) {
#pragma unroll
                for (int j = 0; j < 4; j++) {
                    uint32_t b0 = b[j >> 1][j & 1];
                    uint32_t b1 = b[j >> 1][(j & 1) + 2];
                    asm volatile(
                        "mma.sync.aligned.m16n8k16.row.col.f32.bf16.bf16.f32 "
                        "{%0,%1,%2,%3}, {%4,%5,%6,%7}, {%8,%9}, {%0,%1,%2,%3};"
                        : "+f"(acc[i][j][0]), "+f"(acc[i][j][1]),
                          "+f"(acc[i][j][2]), "+f"(acc[i][j][3])
                        : "r"(a[i][0]), "r"(a[i][1]), "r"(a[i][2]), "r"(a[i][3]),
                          "r"(b0), "r"(b1));
                }
            }
        }
    }

    int lr = lane >> 2, lc = (lane & 3) * 2;
#pragma unroll
    for (int i = 0; i < 4; i++) {
#pragma unroll
        for (int j = 0; j < 4; j++) {
            int mA = m0 + warp_m * 64 + i * 16 + lr;
            int n  = n0 + warp_n * 32 + j * 8 + lc;
            if (mode == 0) {
                float* C = (float*)Cv;
                *(float2*)(C + (size_t)mA * 1024 + n) = make_float2(acc[i][j][0], acc[i][j][1]);
                *(float2*)(C + (size_t)(mA + 8) * 1024 + n) = make_float2(acc[i][j][2], acc[i][j][3]);
            } else {
                // split-head bf16: [B,H,S,128] = [hi(64) | lo(64)]
                __nv_bfloat16* C = (__nv_bfloat16*)Cv;
                int hI = n >> 6, kk2 = n & 63;
                int bA = mA >> 10, sA = mA & 1023;
#pragma unroll
                for (int half = 0; half < 2; half++) {
                    float x0 = acc[i][j][half * 2], x1 = acc[i][j][half * 2 + 1];
                    __nv_bfloat16 h0 = __float2bfloat16(x0), h1 = __float2bfloat16(x1);
                    uint32_t hp = (uint32_t)__bfloat16_as_ushort(h0) |
                                  ((uint32_t)__bfloat16_as_ushort(h1) << 16);
                    uint32_t lq = pack_bf2(x0 - __bfloat162float(h0), x1 - __bfloat162float(h1));
                    size_t base = ((((size_t)bA * Hc + hI) << 10) + sA + half * 8) * 128 + kk2;
                    *(uint32_t*)(C + base)      = hp;
                    *(uint32_t*)(C + base + 64) = lq;
                }
            }
        }
    }
}

// ---------------------------------------------------------------------------
// Tensor-core flash attention, bf16 3-term split for QK^T and PV.
// CTA: one (b,h) x 128-query tile; 256 threads (8 warps, 2m x 4n).
// No online softmax: exp without max-subtraction (logits bounded);
// fully-masked rows (i>=p2 || p1==0) get p=1 for all j -> uniform (matches ref).
// Output written directly in split form into ap ([hi|hi|lo], 3072 cols).
// ---------------------------------------------------------------------------
#define ROWB 272            // smem row stride bytes (128 bf16 data + 8 pad)
#define AT2_SMEM (5*128*ROWB + 512)

__global__ __launch_bounds__(256, 1)
void attn_mma(const __nv_bfloat16* __restrict__ qs, const __nv_bfloat16* __restrict__ ks,
              const __nv_bfloat16* __restrict__ vs, const int* __restrict__ pm1,
              const int* __restrict__ pm2, __nv_bfloat16* __restrict__ ap)
{
    extern __shared__ __align__(128) char smem[];
    uint32_t sb = smem_u32(smem);
    const uint32_t QS = sb;
    const uint32_t KS = sb + 128 * ROWB;
    const uint32_t VS = sb + 2 * 128 * ROWB;
    const uint32_t PH = sb + 3 * 128 * ROWB;
    const uint32_t PL = sb + 4 * 128 * ROWB;
    char* ph_c = smem + 3 * 128 * ROWB;
    char* pl_c = smem + 4 * 128 * ROWB;
    float* Ls = (float*)(smem + 5 * 128 * ROWB);

    int tid = threadIdx.x, lane = tid & 31, wid = tid >> 5;
    int wm = wid >> 2, wn = wid & 3;
    int lm15 = lane & 15, l4 = lane >> 4, lr = lane >> 2, lc = (lane & 3) * 2;
    int bh = blockIdx.y, b = bh >> 4, h = bh & 15;
    int i0 = blockIdx.x * 128;
    int p1 = pm1[b], p2 = pm2[b];

    if (tid < 128) Ls[tid] = 0.f;

    // Q tile load (128 rows x 256B)
    {
        const char* qg = (const char*)(qs + ((size_t)bh * 1024 + i0) * 128);
#pragma unroll
        for (int i = 0; i < 8; i++) {
            int f = i * 256 + tid; int r = f >> 4, c = f & 15;
            asm volatile("cp.async.cg.shared.global [%0], [%1], 16;"
                :: "r"(QS + r * ROWB + c * 16), "l"(qg + r * 256 + c * 16));
        }
        asm volatile("cp.async.commit_group;" ::: "memory");
    }

    float po[4][2][4];
    float lp[4][2];
#pragma unroll
    for (int i = 0; i < 4; i++) {
        lp[i][0] = lp[i][1] = 0.f;
#pragma unroll
        for (int nf = 0; nf < 2; nf++)
#pragma unroll
            for (int r = 0; r < 4; r++) po[i][nf][r] = 0.f;
    }

    for (int jt = 0; jt < 8; jt++) {
        int j0 = jt * 128;
        const char* kg = (const char*)(ks + ((size_t)bh * 1024 + j0) * 128);
        const char* vg = (const char*)(vs + ((size_t)bh * 1024 + j0) * 128);
#pragma unroll
        for (int i = 0; i < 8; i++) {
            int f = i * 256 + tid; int r = f >> 4, c = f & 15;
            asm volatile("cp.async.cg.shared.global [%0], [%1], 16;"
                :: "r"(KS + r * ROWB + c * 16), "l"(kg + r * 256 + c * 16));
            asm volatile("cp.async.cg.shared.global [%0], [%1], 16;"
                :: "r"(VS + r * ROWB + c * 16), "l"(vg + r * 256 + c * 16));
        }
        asm volatile("cp.async.commit_group;" ::: "memory");
        asm volatile("cp.async.wait_group 0;" ::: "memory");
        __syncthreads();

        // ---- S = Qhi*Khi + Qhi*Klo + Qlo*Khi ----
        float acc[4][4][4];
#pragma unroll
        for (int i = 0; i < 4; i++)
#pragma unroll
            for (int j = 0; j < 4; j++)
#pragma unroll
                for (int r = 0; r < 4; r++) acc[i][j][r] = 0.f;

#pragma unroll
        for (int term = 0; term < 3; term++) {
            int qc = (term == 2) ? 8 : 0;
            int kc = (term == 1) ? 8 : 0;
#pragma unroll
            for (int ks4 = 0; ks4 < 4; ks4++) {
                uint32_t a[4][4], bb[2][4];
                int ca = qc + 2 * ks4 + l4;
                int cb = kc + 2 * ks4 + l4;
#pragma unroll
                for (int i = 0; i < 4; i++) {
                    int r = wm * 64 + i * 16 + lm15;
                    asm volatile("ldmatrix.sync.aligned.m8n8.x4.shared.b16 {%0,%1,%2,%3}, [%4];"
                        : "=r"(a[i][0]), "=r"(a[i][1]), "=r"(a[i][2]), "=r"(a[i][3])
                        : "r"(QS + r * ROWB + ca * 16));
                }
#pragma unroll
                for (int g = 0; g < 2; g++) {
                    int r = wn * 32 + g * 16 + lm15;
                    asm volatile("ldmatrix.sync.aligned.m8n8.x4.shared.b16 {%0,%1,%2,%3}, [%4];"
                        : "=r"(bb[g][0]), "=r"(bb[g][1]), "=r"(bb[g][2]), "=r"(bb[g][3])
                        : "r"(KS + r * ROWB + cb * 16));
                }
#pragma unroll
                for (int i = 0; i < 4; i++)
#pragma unroll
                    for (int j = 0; j < 4; j++) {
                        uint32_t b0 = bb[j >> 1][j & 1];
                        uint32_t b1 = bb[j >> 1][(j & 1) + 2];
                        asm volatile(
                            "mma.sync.aligned.m16n8k16.row.col.f32.bf16.bf16.f32 "
                            "{%0,%1,%2,%3}, {%4,%5,%6,%7}, {%8,%9}, {%0,%1,%2,%3};"
                            : "+f"(acc[i][j][0]), "+f"(acc[i][j][1]),
                              "+f"(acc[i][j][2]), "+f"(acc[i][j][3])
                            : "r"(a[i][0]), "r"(a[i][1]), "r"(a[i][2]), "r"(a[i][3]),
                              "r"(b0), "r"(b1));
                    }
            }
        }

        // ---- mask + exp + split to Ph/Pl ----
#pragma unroll
        for (int i = 0; i < 4; i++) {
            int rl = wm * 64 + i * 16 + lr;
            int gi0 = i0 + rl, gi1 = gi0 + 8;
            bool fm0 = (gi0 >= p2) || (p1 == 0);
            bool fm1 = (gi1 >= p2) || (p1 == 0);
#pragma unroll
            for (int j = 0; j < 4; j++) {
                int cl = wn * 32 + j * 8 + lc;
                int gj0 = j0 + cl, gj1 = gj0 + 1;
                float v00 = fm0 ? 1.f : ((gj0 <= gi0 && gj0 < p1) ? __expf(acc[i][j][0] * 0.125f) : 0.f);
                float v01 = fm0 ? 1.f : ((gj1 <= gi0 && gj1 < p1) ? __expf(acc[i][j][1] * 0.125f) : 0.f);
                float v10 = fm1 ? 1.f : ((gj0 <= gi1 && gj0 < p1) ? __expf(acc[i][j][2] * 0.125f) : 0.f);
                float v11 = fm1 ? 1.f : ((gj1 <= gi1 && gj1 < p1) ? __expf(acc[i][j][3] * 0.125f) : 0.f);
                lp[i][0] += v00 + v01;
                lp[i][1] += v10 + v11;

                __nv_bfloat16 h00 = __float2bfloat16(v00), h01 = __float2bfloat16(v01);
                __nv_bfloat16 h10 = __float2bfloat16(v10), h11 = __float2bfloat16(v11);
                uint32_t hp0 = (uint32_t)__bfloat16_as_ushort(h00) | ((uint32_t)__bfloat16_as_ushort(h01) << 16);
                uint32_t hp1 = (uint32_t)__bfloat16_as_ushort(h10) | ((uint32_t)__bfloat16_as_ushort(h11) << 16);
                uint32_t lq0 = pack_bf2(v00 - __bfloat162float(h00), v01 - __bfloat162float(h01));
                uint32_t lq1 = pack_bf2(v10 - __bfloat162float(h10), v11 - __bfloat162float(h11));
                int off0 = rl * ROWB + cl * 2;
                int off1 = (rl + 8) * ROWB + cl * 2;
                *(uint32_t*)(ph_c + off0) = hp0;
                *(uint32_t*)(ph_c + off1) = hp1;
                *(uint32_t*)(pl_c + off0) = lq0;
                *(uint32_t*)(pl_c + off1) = lq1;
            }
        }
        __syncthreads();

        // ---- O += Ph*Vhi + Ph*Vlo + Pl*Vhi ----
#pragma unroll
        for (int term = 0; term < 3; term++) {
            uint32_t PB = (term < 2) ? PH : PL;
            int vc = (term == 1) ? 8 : 0;
#pragma unroll
            for (int ks8 = 0; ks8 < 8; ks8++) {
                uint32_t pa[4][4], bt[4];
                int cpc = 2 * ks8 + l4;
#pragma unroll
                for (int i = 0; i < 4; i++) {
                    int r = wm * 64 + i * 16 + lm15;
                    asm volatile("ldmatrix.sync.aligned.m8n8.x4.shared.b16 {%0,%1,%2,%3}, [%4];"
                        : "=r"(pa[i][0]), "=r"(pa[i][1]), "=r"(pa[i][2]), "=r"(pa[i][3])
                        : "r"(PB + r * ROWB + cpc * 16));
                }
                {
                    int rv = ks8 * 16 + lm15;
                    int cv = vc + wn * 2 + l4;
                    asm volatile("ldmatrix.sync.aligned.m8n8.x4.trans.shared.b16 {%0,%1,%2,%3}, [%4];"
                        : "=r"(bt[0]), "=r"(bt[1]), "=r"(bt[2]), "=r"(bt[3])
                        : "r"(VS + rv * ROWB + cv * 16));
                }
#pragma unroll
                for (int i = 0; i < 4; i++)
#pragma unroll
                    for (int nf = 0; nf < 2; nf++) {
                        asm volatile(
                            "mma.sync.aligned.m16n8k16.row.col.f32.bf16.bf16.f32 "
                            "{%0,%1,%2,%3}, {%4,%5,%6,%7}, {%8,%9}, {%0,%1,%2,%3};"
                            : "+f"(po[i][nf][0]), "+f"(po[i][nf][1]),
                              "+f"(po[i][nf][2]), "+f"(po[i][nf][3])
                            : "r"(pa[i][0]), "r"(pa[i][1]), "r"(pa[i][2]), "r"(pa[i][3]),
                              "r"(bt[nf * 2]), "r"(bt[nf * 2 + 1]));
                    }
            }
        }
        __syncthreads();
    }

    // ---- reduce row sums across quad + 4 n-warps ----
#pragma unroll
    for (int i = 0; i < 4; i++)
#pragma unroll
        for (int hf = 0; hf < 2; hf++) {
            float s = lp[i][hf];
            s += __shfl_xor_sync(0xffffffffu, s, 1);
            s += __shfl_xor_sync(0xffffffffu, s, 2);
            if ((lane & 3) == 0)
                atomicAdd(&Ls[wm * 64 + i * 16 + lr + hf * 8], s);
        }
    __syncthreads();

    // ---- normalize + write split directly into final-GEMM A buffer ----
#pragma unroll
    for (int i = 0; i < 4; i++)
#pragma unroll
        for (int hf = 0; hf < 2; hf++) {
            int row = wm * 64 + i * 16 + lr + hf * 8;
            int sidx = i0 + row;
            float inv = 1.0f / Ls[row];
            size_t mrow = ((size_t)b * 1024 + sidx) * (size_t)KTOT;
#pragma unroll
            for (int nf = 0; nf < 2; nf++) {
                int d = wn * 16 + nf * 8 + lc;
                int col = h * 64 + d;
                float x0 = po[i][nf][hf * 2] * inv;
                float x1 = po[i][nf][hf * 2 + 1] * inv;
                __nv_bfloat16 h0 = __float2bfloat16(x0), h1 = __float2bfloat16(x1);
                uint32_t hp = (uint32_t)__bfloat16_as_ushort(h0) |
                              ((uint32_t)__bfloat16_as_ushort(h1) << 16);
                uint32_t lq = pack_bf2(x0 - __bfloat162float(h0), x1 - __bfloat162float(h1));
                *(uint32_t*)(ap + mrow + col)        = hp;
                *(uint32_t*)(ap + mrow + col + 1024) = hp;
                *(uint32_t*)(ap + mrow + col + 2048) = lq;
            }
        }
}

// ---------------------------------------------------------------------------
extern "C" void kernel_launch(void* const* d_in, const int* in_sizes, int n_in,
                              void* d_out, int out_size)
{
    const float* q   = (const float*)d_in[0];
    const float* k   = (const float*)d_in[1];
    const float* v   = (const float*)d_in[2];
    const int*   pm1 = (const int*)d_in[3];
    const int*   pm2 = (const int*)d_in[4];
    const float* Wq  = (const float*)d_in[5];
    const float* Wk  = (const float*)d_in[6];
    const float* Wv  = (const float*)d_in[7];
    const float* Wo  = (const float*)d_in[8];
    float* out = (float*)d_out;

    __nv_bfloat16 *qs, *ksp, *vsp, *ap, *wp;
    cudaGetSymbolAddress((void**)&qs,  g_qs);
    cudaGetSymbolAddress((void**)&ksp, g_ks);
    cudaGetSymbolAddress((void**)&vsp, g_vs);
    cudaGetSymbolAddress((void**)&ap,  g_ap);
    cudaGetSymbolAddress((void**)&wp,  g_wp);

    cudaFuncSetAttribute(gemm_mma,
        cudaFuncAttributeMaxDynamicSharedMemorySize, GEMM_SMEM);
    cudaFuncSetAttribute(attn_mma,
        cudaFuncAttributeMaxDynamicSharedMemorySize, AT2_SMEM);

    const int A4 = Mrows * 256;
    const int W4 = Dc * 256;
    dim3 gg(Dc / 128, Mrows / 128);   // (8, 64)

    // A split: [hi | hi | lo] -> off_dup=1024, off_lo=2048
    // W split: [hi | lo | hi] -> off_dup=2048, off_lo=1024
    conv_split<<<(W4 + 255) / 256, 256>>>(Wq, wp, W4, 2048, 1024);
    conv_split<<<(A4 + 255) / 256, 256>>>(q, ap, A4, 1024, 2048);
    gemm_mma<<<gg, 256, GEMM_SMEM>>>(ap, wp, (void*)qs, 2);

    conv_split<<<(W4 + 255) / 256, 256>>>(Wk, wp, W4, 2048, 1024);
    conv_split<<<(A4 + 255) / 256, 256>>>(k, ap, A4, 1024, 2048);
    gemm_mma<<<gg, 256, GEMM_SMEM>>>(ap, wp, (void*)ksp, 2);

    conv_split<<<(W4 + 255) / 256, 256>>>(Wv, wp, W4, 2048, 1024);
    conv_split<<<(A4 + 255) / 256, 256>>>(v, ap, A4, 1024, 2048);
    gemm_mma<<<gg, 256, GEMM_SMEM>>>(ap, wp, (void*)vsp, 2);

    // attention: writes split A for final GEMM directly into ap
    attn_mma<<<dim3(Sc / 128, Bc * Hc), 256, AT2_SMEM>>>(qs, ksp, vsp, pm1, pm2, ap);

    // output projection
    conv_split<<<(W4 + 255) / 256, 256>>>(Wo, wp, W4, 2048, 1024);
    gemm_mma<<<gg, 256, GEMM_SMEM>>>(ap, wp, (void*)out, 0);
}

// round 6
// speedup vs baseline: 4.1713x; 1.4265x over previous
#include <cuda_runtime.h>
#include <cuda_bf16.h>
#include <math.h>
#include <stdint.h>

// Problem constants
#define Bc   8
#define Sc   1024
#define Dc   1024
#define Hc   16
#define Mrows (Bc*Sc)      // 8192
#define KROW 2048          // compact split: [hi(1024) | lo(1024)]
#define NSTG 48            // 3 terms x 16 chunks of 64

// ---------------- scratch (device globals: allocation-free) ----------------
__device__ __nv_bfloat16 g_qs[(size_t)Bc*Hc*Sc*128];  // [B,H,S,128]=[hi64|lo64]
__device__ __nv_bfloat16 g_ks[(size_t)Bc*Hc*Sc*128];
__device__ __nv_bfloat16 g_vs[(size_t)Bc*Hc*Sc*128];
__device__ __nv_bfloat16 g_ap[(size_t)Mrows*KROW];    // 32 MB
__device__ __nv_bfloat16 g_wp[(size_t)Dc*KROW];       // 4 MB
__device__ float g_vmean[Bc*Hc*64];

__device__ __forceinline__ uint32_t smem_u32(const void* p) {
    uint32_t a;
    asm("{ .reg .u64 t; cvta.to.shared.u64 t, %1; cvt.u32.u64 %0, t; }"
        : "=r"(a) : "l"(p));
    return a;
}

__device__ __forceinline__ uint32_t pack_bf2(float a, float b) {
    __nv_bfloat16 ha = __float2bfloat16(a), hb = __float2bfloat16(b);
    return (uint32_t)__bfloat16_as_ushort(ha) | ((uint32_t)__bfloat16_as_ushort(hb) << 16);
}

// ---------------------------------------------------------------------------
// fp32 -> bf16 compact split: hi at [c], lo at [1024+c]; Y row = 2048 bf16
// ---------------------------------------------------------------------------
__global__ __launch_bounds__(256) void conv_split(
    const float* __restrict__ X, __nv_bfloat16* __restrict__ Y, int total4)
{
    int i = blockIdx.x * 256 + threadIdx.x;
    if (i >= total4) return;
    int r = i >> 8;
    int c4 = (i & 255) << 2;
    float4 x = *(const float4*)(X + (size_t)r * 1024 + c4);

    __nv_bfloat16 h0 = __float2bfloat16(x.x), h1 = __float2bfloat16(x.y);
    __nv_bfloat16 h2 = __float2bfloat16(x.z), h3 = __float2bfloat16(x.w);
    uint32_t hA = (uint32_t)__bfloat16_as_ushort(h0) | ((uint32_t)__bfloat16_as_ushort(h1) << 16);
    uint32_t hB = (uint32_t)__bfloat16_as_ushort(h2) | ((uint32_t)__bfloat16_as_ushort(h3) << 16);
    uint32_t lA = pack_bf2(x.x - __bfloat162float(h0), x.y - __bfloat162float(h1));
    uint32_t lB = pack_bf2(x.z - __bfloat162float(h2), x.w - __bfloat162float(h3));

    size_t base = (size_t)r * KROW;
    *(uint2*)(Y + base + c4)        = make_uint2(hA, hB);
    *(uint2*)(Y + base + 1024 + c4) = make_uint2(lA, lB);
}

// ---------------------------------------------------------------------------
// bf16 mma.sync GEMM over compact splits. Stage t -> (term,chunk):
//   term0: Ahi*Whi, term1: Ahi*Wlo, term2: Alo*Whi
// CTA 128x128x64-per-stage, 3-stage cp.async, 256 threads, warp 64x32.
// mode 0: C fp32 [M,1024]; mode 2: C bf16 split-head [B,H,S,128]
// ---------------------------------------------------------------------------
#define SLOT_BYTES 32768
#define GEMM_SMEM (3 * SLOT_BYTES)

__device__ __forceinline__ void stage_off(int t, int& ao, int& wo) {
    int term = t >> 4, chunk = t & 15;
    ao = ((term == 2) ? 1024 : 0) + chunk * 64;
    wo = ((term == 1) ? 1024 : 0) + chunk * 64;
}

__device__ __forceinline__ void load_stage_mma(
    const __nv_bfloat16* __restrict__ Ap, const __nv_bfloat16* __restrict__ Wp,
    uint32_t abase, uint32_t bbase, int m0, int n0, int t, int tid)
{
    int ao, wo;
    stage_off(t, ao, wo);
#pragma unroll
    for (int i = 0; i < 4; i++) {
        int f = i * 256 + tid;
        int r = f >> 3, cx = f & 7;
        uint32_t sw = r * 128 + ((cx ^ (r & 7)) << 4);
        const void* ga = Ap + (size_t)(m0 + r) * KROW + ao + cx * 8;
        asm volatile("cp.async.cg.shared.global [%0], [%1], 16;" :: "r"(abase + sw), "l"(ga));
        const void* gb = Wp + (size_t)(n0 + r) * KROW + wo + cx * 8;
        asm volatile("cp.async.cg.shared.global [%0], [%1], 16;" :: "r"(bbase + sw), "l"(gb));
    }
}

__global__ __launch_bounds__(256, 2)
void gemm_mma(const __nv_bfloat16* __restrict__ Ap, const __nv_bfloat16* __restrict__ Wp,
              void* __restrict__ Cv, int mode)
{
    extern __shared__ __align__(128) char smem[];
    uint32_t sb = smem_u32(smem);
    int tid = threadIdx.x;
    int wid = tid >> 5, lane = tid & 31;
    int warp_m = wid >> 2, warp_n = wid & 3;
    int m0 = blockIdx.y * 128, n0 = blockIdx.x * 128;

    float acc[4][4][4];
#pragma unroll
    for (int i = 0; i < 4; i++)
#pragma unroll
        for (int j = 0; j < 4; j++)
#pragma unroll
            for (int r = 0; r < 4; r++) acc[i][j][r] = 0.f;

    load_stage_mma(Ap, Wp, sb, sb + 16384, m0, n0, 0, tid);
    asm volatile("cp.async.commit_group;" ::: "memory");
    load_stage_mma(Ap, Wp, sb + SLOT_BYTES, sb + SLOT_BYTES + 16384, m0, n0, 1, tid);
    asm volatile("cp.async.commit_group;" ::: "memory");

    int lm15 = lane & 15, l4 = lane >> 4;

    for (int s = 0; s < NSTG; s++) {
        asm volatile("cp.async.wait_group 1;" ::: "memory");
        __syncthreads();

        if (s + 2 < NSTG) {
            uint32_t ab = sb + ((s + 2) % 3) * SLOT_BYTES;
            load_stage_mma(Ap, Wp, ab, ab + 16384, m0, n0, s + 2, tid);
        }
        asm volatile("cp.async.commit_group;" ::: "memory");

        uint32_t As = sb + (s % 3) * SLOT_BYTES;
        uint32_t Bs = As + 16384;

#pragma unroll
        for (int kk = 0; kk < 4; kk++) {
            int c0 = 2 * kk + l4;
            uint32_t a[4][4], b[2][4];
#pragma unroll
            for (int i = 0; i < 4; i++) {
                int r = warp_m * 64 + i * 16 + lm15;
                uint32_t addr = As + r * 128 + ((c0 ^ (r & 7)) << 4);
                asm volatile("ldmatrix.sync.aligned.m8n8.x4.shared.b16 {%0,%1,%2,%3}, [%4];"
                    : "=r"(a[i][0]), "=r"(a[i][1]), "=r"(a[i][2]), "=r"(a[i][3]) : "r"(addr));
            }
#pragma unroll
            for (int g = 0; g < 2; g++) {
                int r = warp_n * 32 + g * 16 + lm15;
                uint32_t addr = Bs + r * 128 + ((c0 ^ (r & 7)) << 4);
                asm volatile("ldmatrix.sync.aligned.m8n8.x4.shared.b16 {%0,%1,%2,%3}, [%4];"
                    : "=r"(b[g][0]), "=r"(b[g][1]), "=r"(b[g][2]), "=r"(b[g][3]) : "r"(addr));
            }
#pragma unroll
            for (int i = 0; i < 4; i++) {
#pragma unroll
                for (int j = 0; j < 4; j++) {
                    uint32_t b0 = b[j >> 1][j & 1];
                    uint32_t b1 = b[j >> 1][(j & 1) + 2];
                    asm volatile(
                        "mma.sync.aligned.m16n8k16.row.col.f32.bf16.bf16.f32 "
                        "{%0,%1,%2,%3}, {%4,%5,%6,%7}, {%8,%9}, {%0,%1,%2,%3};"
                        : "+f"(acc[i][j][0]), "+f"(acc[i][j][1]),
                          "+f"(acc[i][j][2]), "+f"(acc[i][j][3])
                        : "r"(a[i][0]), "r"(a[i][1]), "r"(a[i][2]), "r"(a[i][3]),
                          "r"(b0), "r"(b1));
                }
            }
        }
    }

    int lr = lane >> 2, lc = (lane & 3) * 2;
#pragma unroll
    for (int i = 0; i < 4; i++) {
#pragma unroll
        for (int j = 0; j < 4; j++) {
            int mA = m0 + warp_m * 64 + i * 16 + lr;
            int n  = n0 + warp_n * 32 + j * 8 + lc;
            if (mode == 0) {
                float* C = (float*)Cv;
                *(float2*)(C + (size_t)mA * 1024 + n) = make_float2(acc[i][j][0], acc[i][j][1]);
                *(float2*)(C + (size_t)(mA + 8) * 1024 + n) = make_float2(acc[i][j][2], acc[i][j][3]);
            } else {
                __nv_bfloat16* C = (__nv_bfloat16*)Cv;
                int hI = n >> 6, kk2 = n & 63;
                int bA = mA >> 10, sA = mA & 1023;
#pragma unroll
                for (int half = 0; half < 2; half++) {
                    float x0 = acc[i][j][half * 2], x1 = acc[i][j][half * 2 + 1];
                    __nv_bfloat16 h0 = __float2bfloat16(x0), h1 = __float2bfloat16(x1);
                    uint32_t hp = (uint32_t)__bfloat16_as_ushort(h0) |
                                  ((uint32_t)__bfloat16_as_ushort(h1) << 16);
                    uint32_t lq = pack_bf2(x0 - __bfloat162float(h0), x1 - __bfloat162float(h1));
                    size_t base = ((((size_t)bA * Hc + hI) << 10) + sA + half * 8) * 128 + kk2;
                    *(uint32_t*)(C + base)      = hp;
                    *(uint32_t*)(C + base + 64) = lq;
                }
            }
        }
    }
}

// ---------------------------------------------------------------------------
// Vmean[b,h,d] = mean over s of (vhi+vlo) — the uniform-softmax output
// ---------------------------------------------------------------------------
__global__ __launch_bounds__(256) void vmean_kernel(
    const __nv_bfloat16* __restrict__ vs, float* __restrict__ vmean)
{
    __shared__ float smv[64];
    int bh = blockIdx.x;
    int tid = threadIdx.x, lane = tid & 31, wid = tid >> 5;
    if (tid < 64) smv[tid] = 0.f;
    __syncthreads();

    int oct = lane & 15;       // 16B-chunk index within a 256B row
    int rsel = lane >> 4;      // which of 2 rows per warp-iter
    float acc[8];
#pragma unroll
    for (int k = 0; k < 8; k++) acc[k] = 0.f;

    const uint4* base = (const uint4*)(vs + (size_t)bh * 1024 * 128);
    for (int s = wid * 2 + rsel; s < 1024; s += 16) {
        uint4 xv = base[s * 16 + oct];
        const __nv_bfloat16* p = (const __nv_bfloat16*)&xv;
#pragma unroll
        for (int k = 0; k < 8; k++) acc[k] += __bfloat162float(p[k]);
    }
    // combine hi (oct<8) with lo (oct>=8): lanes l and l^8 hold same d-range
#pragma unroll
    for (int k = 0; k < 8; k++) acc[k] += __shfl_xor_sync(0xffffffffu, acc[k], 8);
    if (oct < 8) {
#pragma unroll
        for (int k = 0; k < 8; k++) atomicAdd(&smv[oct * 8 + k], acc[k]);
    }
    __syncthreads();
    if (tid < 64) vmean[bh * 64 + tid] = smv[tid] * (1.0f / 1024.0f);
}

// ---------------------------------------------------------------------------
// FA2-style tensor-core attention, 3-term bf16 split, tile skipping,
// register-resident P, double-buffered K/V.
// 8 warps x 16 query rows each; CTA = (b,h) x 128-query tile.
// ---------------------------------------------------------------------------
#define ROWB 272
#define TILEB (128 * ROWB)          // 34816
#define AT_SMEM (5 * TILEB)         // Q + 2x(K,V)

__global__ __launch_bounds__(256, 1)
void attn_mma(const __nv_bfloat16* __restrict__ qs, const __nv_bfloat16* __restrict__ ks,
              const __nv_bfloat16* __restrict__ vs, const int* __restrict__ pm1,
              const int* __restrict__ pm2, const float* __restrict__ vmean,
              __nv_bfloat16* __restrict__ ap)
{
    extern __shared__ __align__(128) char smem[];
    uint32_t sb = smem_u32(smem);
    const uint32_t QS = sb;

    int tid = threadIdx.x, lane = tid & 31, w = tid >> 5;
    int lm15 = lane & 15, l4 = lane >> 4, lr = lane >> 2, lc = (lane & 3) * 2;
    int bh = blockIdx.y, b = bh >> 4, h = bh & 15;
    int i0 = blockIdx.x * 128;
    int p1 = pm1[b], p2 = pm2[b];

    int rw = w * 16;
    int gi0 = i0 + rw + lr, gi1 = gi0 + 8;
    bool fm0 = (gi0 >= p2) || (p1 == 0);
    bool fm1 = (gi1 >= p2) || (p1 == 0);

    int jt_max = 0;
    if (!((i0 >= p2) || (p1 == 0))) {
        int J = min(i0 + 128, p1);          // keys j < J are live
        jt_max = (J + 127) >> 7;
    }

    float po[8][4];
#pragma unroll
    for (int nb = 0; nb < 8; nb++)
#pragma unroll
        for (int r = 0; r < 4; r++) po[nb][r] = 0.f;
    float ls0 = 0.f, ls1 = 0.f;

    if (jt_max > 0) {
        // Q tile
        {
            const char* qg = (const char*)(qs + ((size_t)bh * 1024 + i0) * 128);
#pragma unroll
            for (int i = 0; i < 8; i++) {
                int f = i * 256 + tid; int r = f >> 4, c = f & 15;
                asm volatile("cp.async.cg.shared.global [%0], [%1], 16;"
                    :: "r"(QS + r * ROWB + c * 16), "l"(qg + r * 256 + c * 16));
            }
            asm volatile("cp.async.commit_group;" ::: "memory");
        }
        // tile 0 into buffer 0
        {
            const char* kg = (const char*)(ks + (size_t)bh * 1024 * 128);
            const char* vg = (const char*)(vs + (size_t)bh * 1024 * 128);
            uint32_t KB = sb + TILEB, VB = sb + 2 * TILEB;
#pragma unroll
            for (int i = 0; i < 8; i++) {
                int f = i * 256 + tid; int r = f >> 4, c = f & 15;
                asm volatile("cp.async.cg.shared.global [%0], [%1], 16;"
                    :: "r"(KB + r * ROWB + c * 16), "l"(kg + r * 256 + c * 16));
                asm volatile("cp.async.cg.shared.global [%0], [%1], 16;"
                    :: "r"(VB + r * ROWB + c * 16), "l"(vg + r * 256 + c * 16));
            }
            asm volatile("cp.async.commit_group;" ::: "memory");
        }

        for (int jt = 0; jt < jt_max; jt++) {
            int j0 = jt * 128;
            if (jt + 1 < jt_max) {
                int jn = (jt + 1) & 1;
                uint32_t KB = sb + (1 + 2 * jn) * TILEB;
                uint32_t VB = KB + TILEB;
                const char* kg = (const char*)(ks + ((size_t)bh * 1024 + (jt + 1) * 128) * 128);
                const char* vg = (const char*)(vs + ((size_t)bh * 1024 + (jt + 1) * 128) * 128);
#pragma unroll
                for (int i = 0; i < 8; i++) {
                    int f = i * 256 + tid; int r = f >> 4, c = f & 15;
                    asm volatile("cp.async.cg.shared.global [%0], [%1], 16;"
                        :: "r"(KB + r * ROWB + c * 16), "l"(kg + r * 256 + c * 16));
                    asm volatile("cp.async.cg.shared.global [%0], [%1], 16;"
                        :: "r"(VB + r * ROWB + c * 16), "l"(vg + r * 256 + c * 16));
                }
                asm volatile("cp.async.commit_group;" ::: "memory");
                asm volatile("cp.async.wait_group 1;" ::: "memory");
            } else {
                asm volatile("cp.async.wait_group 0;" ::: "memory");
            }
            __syncthreads();

            uint32_t KS = sb + (1 + 2 * (jt & 1)) * TILEB;
            uint32_t VS = KS + TILEB;

            // ---- S = Qhi*Khi + Qhi*Klo + Qlo*Khi ----
            float sc[16][4];
#pragma unroll
            for (int nb = 0; nb < 16; nb++)
#pragma unroll
                for (int r = 0; r < 4; r++) sc[nb][r] = 0.f;

#pragma unroll
            for (int term = 0; term < 3; term++) {
                int qc = (term == 2) ? 8 : 0;
                int kc = (term == 1) ? 8 : 0;
#pragma unroll
                for (int ks4 = 0; ks4 < 4; ks4++) {
                    uint32_t a[4], bb[8][4];
                    int ca = qc + 2 * ks4 + l4;
                    int cb = kc + 2 * ks4 + l4;
                    asm volatile("ldmatrix.sync.aligned.m8n8.x4.shared.b16 {%0,%1,%2,%3}, [%4];"
                        : "=r"(a[0]), "=r"(a[1]), "=r"(a[2]), "=r"(a[3])
                        : "r"(QS + (rw + lm15) * ROWB + ca * 16));
#pragma unroll
                    for (int g = 0; g < 8; g++) {
                        asm volatile("ldmatrix.sync.aligned.m8n8.x4.shared.b16 {%0,%1,%2,%3}, [%4];"
                            : "=r"(bb[g][0]), "=r"(bb[g][1]), "=r"(bb[g][2]), "=r"(bb[g][3])
                            : "r"(KS + (g * 16 + lm15) * ROWB + cb * 16));
                    }
#pragma unroll
                    for (int nb = 0; nb < 16; nb++) {
                        uint32_t b0 = bb[nb >> 1][nb & 1];
                        uint32_t b1 = bb[nb >> 1][(nb & 1) + 2];
                        asm volatile(
                            "mma.sync.aligned.m16n8k16.row.col.f32.bf16.bf16.f32 "
                            "{%0,%1,%2,%3}, {%4,%5,%6,%7}, {%8,%9}, {%0,%1,%2,%3};"
                            : "+f"(sc[nb][0]), "+f"(sc[nb][1]), "+f"(sc[nb][2]), "+f"(sc[nb][3])
                            : "r"(a[0]), "r"(a[1]), "r"(a[2]), "r"(a[3]), "r"(b0), "r"(b1));
                    }
                }
            }

            // ---- mask + exp (no max needed; logits bounded, masked -> 0) ----
#pragma unroll
            for (int nb = 0; nb < 16; nb++) {
                int cl = nb * 8 + lc;
                int gj0 = j0 + cl, gj1 = gj0 + 1;
                float v00 = (!fm0 && gj0 <= gi0 && gj0 < p1) ? __expf(sc[nb][0] * 0.125f) : 0.f;
                float v01 = (!fm0 && gj1 <= gi0 && gj1 < p1) ? __expf(sc[nb][1] * 0.125f) : 0.f;
                float v10 = (!fm1 && gj0 <= gi1 && gj0 < p1) ? __expf(sc[nb][2] * 0.125f) : 0.f;
                float v11 = (!fm1 && gj1 <= gi1 && gj1 < p1) ? __expf(sc[nb][3] * 0.125f) : 0.f;
                ls0 += v00 + v01;
                ls1 += v10 + v11;
                sc[nb][0] = v00; sc[nb][1] = v01; sc[nb][2] = v10; sc[nb][3] = v11;
            }

            // ---- O += Ph*Vhi + Ph*Vlo + Pl*Vhi  (P from registers) ----
#pragma unroll
            for (int t = 0; t < 8; t++) {
                uint32_t ahi[4], alo[4];
#pragma unroll
                for (int half = 0; half < 2; half++) {   // nb = 2t + half -> k-half
                    float* s4 = sc[2 * t + half];
                    __nv_bfloat16 h0 = __float2bfloat16(s4[0]), h1 = __float2bfloat16(s4[1]);
                    __nv_bfloat16 h2 = __float2bfloat16(s4[2]), h3 = __float2bfloat16(s4[3]);
                    ahi[half * 2]     = (uint32_t)__bfloat16_as_ushort(h0) | ((uint32_t)__bfloat16_as_ushort(h1) << 16);
                    ahi[half * 2 + 1] = (uint32_t)__bfloat16_as_ushort(h2) | ((uint32_t)__bfloat16_as_ushort(h3) << 16);
                    alo[half * 2]     = pack_bf2(s4[0] - __bfloat162float(h0), s4[1] - __bfloat162float(h1));
                    alo[half * 2 + 1] = pack_bf2(s4[2] - __bfloat162float(h2), s4[3] - __bfloat162float(h3));
                }
                // note A-frag order: {r,k0}, {r+8,k0}, {r,k8}, {r+8,k8}
                uint32_t af_hi[4] = { ahi[0], ahi[1], ahi[2], ahi[3] };
                uint32_t af_lo[4] = { alo[0], alo[1], alo[2], alo[3] };

                uint32_t bth[4][4], btl[4][4];
#pragma unroll
                for (int db = 0; db < 4; db++) {
                    int rv = t * 16 + lm15;
                    asm volatile("ldmatrix.sync.aligned.m8n8.x4.trans.shared.b16 {%0,%1,%2,%3}, [%4];"
                        : "=r"(bth[db][0]), "=r"(bth[db][1]), "=r"(bth[db][2]), "=r"(bth[db][3])
                        : "r"(VS + rv * ROWB + (db * 2 + l4) * 16));
                    asm volatile("ldmatrix.sync.aligned.m8n8.x4.trans.shared.b16 {%0,%1,%2,%3}, [%4];"
                        : "=r"(btl[db][0]), "=r"(btl[db][1]), "=r"(btl[db][2]), "=r"(btl[db][3])
                        : "r"(VS + rv * ROWB + (8 + db * 2 + l4) * 16));
                }
#pragma unroll
                for (int db = 0; db < 4; db++)
#pragma unroll
                    for (int nf = 0; nf < 2; nf++) {
                        int nb = db * 2 + nf;
                        asm volatile(
                            "mma.sync.aligned.m16n8k16.row.col.f32.bf16.bf16.f32 "
                            "{%0,%1,%2,%3}, {%4,%5,%6,%7}, {%8,%9}, {%0,%1,%2,%3};"
                            : "+f"(po[nb][0]), "+f"(po[nb][1]), "+f"(po[nb][2]), "+f"(po[nb][3])
                            : "r"(af_hi[0]), "r"(af_hi[1]), "r"(af_hi[2]), "r"(af_hi[3]),
                              "r"(bth[db][nf * 2]), "r"(bth[db][nf * 2 + 1]));
                        asm volatile(
                            "mma.sync.aligned.m16n8k16.row.col.f32.bf16.bf16.f32 "
                            "{%0,%1,%2,%3}, {%4,%5,%6,%7}, {%8,%9}, {%0,%1,%2,%3};"
                            : "+f"(po[nb][0]), "+f"(po[nb][1]), "+f"(po[nb][2]), "+f"(po[nb][3])
                            : "r"(af_hi[0]), "r"(af_hi[1]), "r"(af_hi[2]), "r"(af_hi[3]),
                              "r"(btl[db][nf * 2]), "r"(btl[db][nf * 2 + 1]));
                        asm volatile(
                            "mma.sync.aligned.m16n8k16.row.col.f32.bf16.bf16.f32 "
                            "{%0,%1,%2,%3}, {%4,%5,%6,%7}, {%8,%9}, {%0,%1,%2,%3};"
                            : "+f"(po[nb][0]), "+f"(po[nb][1]), "+f"(po[nb][2]), "+f"(po[nb][3])
                            : "r"(af_lo[0]), "r"(af_lo[1]), "r"(af_lo[2]), "r"(af_lo[3]),
                              "r"(bth[db][nf * 2]), "r"(bth[db][nf * 2 + 1]));
                    }
            }
            __syncthreads();
        }
    }

    // ---- row-sum reduce within 4-lane groups ----
    ls0 += __shfl_xor_sync(0xffffffffu, ls0, 1);
    ls0 += __shfl_xor_sync(0xffffffffu, ls0, 2);
    ls1 += __shfl_xor_sync(0xffffffffu, ls1, 1);
    ls1 += __shfl_xor_sync(0xffffffffu, ls1, 2);
    float inv0 = fm0 ? 0.f : 1.0f / ls0;
    float inv1 = fm1 ? 0.f : 1.0f / ls1;

    // ---- write split output directly into final-GEMM A buffer ----
    size_t mr0 = ((size_t)b * 1024 + (i0 + rw + lr)) * (size_t)KROW;
    size_t mr1 = ((size_t)b * 1024 + (i0 + rw + lr + 8)) * (size_t)KROW;
#pragma unroll
    for (int nb = 0; nb < 8; nb++) {
        int d = nb * 8 + lc;
        int col = h * 64 + d;
        float x0, x1, y0, y1;
        if (fm0) { x0 = vmean[bh * 64 + d]; x1 = vmean[bh * 64 + d + 1]; }
        else     { x0 = po[nb][0] * inv0;   x1 = po[nb][1] * inv0; }
        if (fm1) { y0 = vmean[bh * 64 + d]; y1 = vmean[bh * 64 + d + 1]; }
        else     { y0 = po[nb][2] * inv1;   y1 = po[nb][3] * inv1; }

        __nv_bfloat16 hx0 = __float2bfloat16(x0), hx1 = __float2bfloat16(x1);
        uint32_t hp0 = (uint32_t)__bfloat16_as_ushort(hx0) | ((uint32_t)__bfloat16_as_ushort(hx1) << 16);
        uint32_t lq0 = pack_bf2(x0 - __bfloat162float(hx0), x1 - __bfloat162float(hx1));
        __nv_bfloat16 hy0 = __float2bfloat16(y0), hy1 = __float2bfloat16(y1);
        uint32_t hp1 = (uint32_t)__bfloat16_as_ushort(hy0) | ((uint32_t)__bfloat16_as_ushort(hy1) << 16);
        uint32_t lq1 = pack_bf2(y0 - __bfloat162float(hy0), y1 - __bfloat162float(hy1));

        *(uint32_t*)(ap + mr0 + col)        = hp0;
        *(uint32_t*)(ap + mr0 + col + 1024) = lq0;
        *(uint32_t*)(ap + mr1 + col)        = hp1;
        *(uint32_t*)(ap + mr1 + col + 1024) = lq1;
    }
}

// ---------------------------------------------------------------------------
extern "C" void kernel_launch(void* const* d_in, const int* in_sizes, int n_in,
                              void* d_out, int out_size)
{
    const float* q   = (const float*)d_in[0];
    const float* k   = (const float*)d_in[1];
    const float* v   = (const float*)d_in[2];
    const int*   pm1 = (const int*)d_in[3];
    const int*   pm2 = (const int*)d_in[4];
    const float* Wq  = (const float*)d_in[5];
    const float* Wk  = (const float*)d_in[6];
    const float* Wv  = (const float*)d_in[7];
    const float* Wo  = (const float*)d_in[8];
    float* out = (float*)d_out;

    __nv_bfloat16 *qs, *ksp, *vsp, *ap, *wp;
    float* vmean;
    cudaGetSymbolAddress((void**)&qs,    g_qs);
    cudaGetSymbolAddress((void**)&ksp,   g_ks);
    cudaGetSymbolAddress((void**)&vsp,   g_vs);
    cudaGetSymbolAddress((void**)&ap,    g_ap);
    cudaGetSymbolAddress((void**)&wp,    g_wp);
    cudaGetSymbolAddress((void**)&vmean, g_vmean);

    cudaFuncSetAttribute(gemm_mma,
        cudaFuncAttributeMaxDynamicSharedMemorySize, GEMM_SMEM);
    cudaFuncSetAttribute(attn_mma,
        cudaFuncAttributeMaxDynamicSharedMemorySize, AT_SMEM);

    const int A4 = Mrows * 256;
    const int W4 = Dc * 256;
    dim3 gg(Dc / 128, Mrows / 128);   // (8, 64)

    conv_split<<<(W4 + 255) / 256, 256>>>(Wq, wp, W4);
    conv_split<<<(A4 + 255) / 256, 256>>>(q, ap, A4);
    gemm_mma<<<gg, 256, GEMM_SMEM>>>(ap, wp, (void*)qs, 2);

    conv_split<<<(W4 + 255) / 256, 256>>>(Wk, wp, W4);
    conv_split<<<(A4 + 255) / 256, 256>>>(k, ap, A4);
    gemm_mma<<<gg, 256, GEMM_SMEM>>>(ap, wp, (void*)ksp, 2);

    conv_split<<<(W4 + 255) / 256, 256>>>(Wv, wp, W4);
    conv_split<<<(A4 + 255) / 256, 256>>>(v, ap, A4);
    gemm_mma<<<gg, 256, GEMM_SMEM>>>(ap, wp, (void*)vsp, 2);

    vmean_kernel<<<Bc * Hc, 256>>>(vsp, vmean);

    // attention writes split A for the final GEMM directly into ap
    attn_mma<<<dim3(Sc / 128, Bc * Hc), 256, AT_SMEM>>>(qs, ksp, vsp, pm1, pm2, vmean, ap);

    conv_split<<<(W4 + 255) / 256, 256>>>(Wo, wp, W4);
    gemm_mma<<<gg, 256, GEMM_SMEM>>>(ap, wp, (void*)out, 0);
}

// round 7
// speedup vs baseline: 4.4156x; 1.0586x over previous
#include <cuda_runtime.h>
#include <cuda_bf16.h>
#include <math.h>
#include <stdint.h>

// Problem constants
#define Bc   8
#define Sc   1024
#define Dc   1024
#define Hc   16
#define Mrows (Bc*Sc)      // 8192
#define KROW 2048          // compact split: [hi(1024) | lo(1024)]
#define NCH  16            // 16 K-chunks of 64

// ---------------- scratch (device globals: allocation-free) ----------------
__device__ __nv_bfloat16 g_qs[(size_t)Bc*Hc*Sc*128];  // [B,H,S,128]=[hi64|lo64]
__device__ __nv_bfloat16 g_ks[(size_t)Bc*Hc*Sc*128];
__device__ __nv_bfloat16 g_vs[(size_t)Bc*Hc*Sc*128];
__device__ __nv_bfloat16 g_ap[(size_t)Mrows*KROW];    // 32 MB
__device__ __nv_bfloat16 g_wp[(size_t)4*Dc*KROW];     // 16 MB (Wq,Wk,Wv,Wo)
__device__ float g_vmean[Bc*Hc*64];

__device__ __forceinline__ uint32_t smem_u32(const void* p) {
    uint32_t a;
    asm("{ .reg .u64 t; cvta.to.shared.u64 t, %1; cvt.u32.u64 %0, t; }"
        : "=r"(a) : "l"(p));
    return a;
}

__device__ __forceinline__ uint32_t pack_bf2(float a, float b) {
    __nv_bfloat16 ha = __float2bfloat16(a), hb = __float2bfloat16(b);
    return (uint32_t)__bfloat16_as_ushort(ha) | ((uint32_t)__bfloat16_as_ushort(hb) << 16);
}

// ---------------------------------------------------------------------------
// fp32 -> bf16 compact split, 8 floats/thread, 16B stores.
// ---------------------------------------------------------------------------
__global__ __launch_bounds__(256) void conv_split8(
    const float* __restrict__ X, __nv_bfloat16* __restrict__ Y, int total8)
{
    int i = blockIdx.x * 256 + threadIdx.x;
    if (i >= total8) return;
    int r = i >> 7;
    int c8 = (i & 127) << 3;
    const float* src = X + (size_t)r * 1024 + c8;
    float4 x0 = *(const float4*)src;
    float4 x1 = *(const float4*)(src + 4);

    __nv_bfloat16 h0 = __float2bfloat16(x0.x), h1 = __float2bfloat16(x0.y);
    __nv_bfloat16 h2 = __float2bfloat16(x0.z), h3 = __float2bfloat16(x0.w);
    __nv_bfloat16 h4 = __float2bfloat16(x1.x), h5 = __float2bfloat16(x1.y);
    __nv_bfloat16 h6 = __float2bfloat16(x1.z), h7 = __float2bfloat16(x1.w);

    uint4 hv, lv;
    hv.x = (uint32_t)__bfloat16_as_ushort(h0) | ((uint32_t)__bfloat16_as_ushort(h1) << 16);
    hv.y = (uint32_t)__bfloat16_as_ushort(h2) | ((uint32_t)__bfloat16_as_ushort(h3) << 16);
    hv.z = (uint32_t)__bfloat16_as_ushort(h4) | ((uint32_t)__bfloat16_as_ushort(h5) << 16);
    hv.w = (uint32_t)__bfloat16_as_ushort(h6) | ((uint32_t)__bfloat16_as_ushort(h7) << 16);
    lv.x = pack_bf2(x0.x - __bfloat162float(h0), x0.y - __bfloat162float(h1));
    lv.y = pack_bf2(x0.z - __bfloat162float(h2), x0.w - __bfloat162float(h3));
    lv.z = pack_bf2(x1.x - __bfloat162float(h4), x1.y - __bfloat162float(h5));
    lv.w = pack_bf2(x1.z - __bfloat162float(h6), x1.w - __bfloat162float(h7));

    size_t base = (size_t)r * KROW;
    *(uint4*)(Y + base + c8)        = hv;
    *(uint4*)(Y + base + 1024 + c8) = lv;
}

// Batched W conversion: 4 weight matrices in one launch (blockIdx.y selects)
__global__ __launch_bounds__(256) void conv_w_all(
    const float* __restrict__ W0, const float* __restrict__ W1,
    const float* __restrict__ W2, const float* __restrict__ W3,
    __nv_bfloat16* __restrict__ Y)
{
    const float* X = (blockIdx.y == 0) ? W0 : (blockIdx.y == 1) ? W1
                   : (blockIdx.y == 2) ? W2 : W3;
    int i = blockIdx.x * 256 + threadIdx.x;   // 131072 per matrix
    int r = i >> 7;
    int c8 = (i & 127) << 3;
    const float* src = X + (size_t)r * 1024 + c8;
    float4 x0 = *(const float4*)src;
    float4 x1 = *(const float4*)(src + 4);

    __nv_bfloat16 h0 = __float2bfloat16(x0.x), h1 = __float2bfloat16(x0.y);
    __nv_bfloat16 h2 = __float2bfloat16(x0.z), h3 = __float2bfloat16(x0.w);
    __nv_bfloat16 h4 = __float2bfloat16(x1.x), h5 = __float2bfloat16(x1.y);
    __nv_bfloat16 h6 = __float2bfloat16(x1.z), h7 = __float2bfloat16(x1.w);

    uint4 hv, lv;
    hv.x = (uint32_t)__bfloat16_as_ushort(h0) | ((uint32_t)__bfloat16_as_ushort(h1) << 16);
    hv.y = (uint32_t)__bfloat16_as_ushort(h2) | ((uint32_t)__bfloat16_as_ushort(h3) << 16);
    hv.z = (uint32_t)__bfloat16_as_ushort(h4) | ((uint32_t)__bfloat16_as_ushort(h5) << 16);
    hv.w = (uint32_t)__bfloat16_as_ushort(h6) | ((uint32_t)__bfloat16_as_ushort(h7) << 16);
    lv.x = pack_bf2(x0.x - __bfloat162float(h0), x0.y - __bfloat162float(h1));
    lv.y = pack_bf2(x0.z - __bfloat162float(h2), x0.w - __bfloat162float(h3));
    lv.z = pack_bf2(x1.x - __bfloat162float(h4), x1.y - __bfloat162float(h5));
    lv.w = pack_bf2(x1.z - __bfloat162float(h6), x1.w - __bfloat162float(h7));

    size_t base = (size_t)blockIdx.y * Dc * KROW + (size_t)r * KROW;
    *(uint4*)(Y + base + c8)        = hv;
    *(uint4*)(Y + base + 1024 + c8) = lv;
}

// ---------------------------------------------------------------------------
// Chunk-fused bf16 split GEMM: C[8192,1024] = A[8192,(hi|lo)] * W[1024,(hi|lo)]^T
// CTA tile 128x256, 16 chunk-stages (Ahi,Alo,Whi,Wlo staged together),
// double-buffered (2x96KB), 256 threads (8 warps, 2m x 4n, warp 64x64).
// Terms: Ahi*Whi + Ahi*Wlo + Alo*Whi. A-hi fragments shared across 2 terms.
// mode 0: C fp32 [M,1024]; mode 2: C bf16 split-head [B,H,S,128]
// ---------------------------------------------------------------------------
#define STAGE_B 98304                      // 96KB: Ahi 16K | Alo 16K | Whi 32K | Wlo 32K
#define GEMM_SMEM (2 * STAGE_B)            // 192KB

__device__ __forceinline__ void load_chunk(
    const __nv_bfloat16* __restrict__ Ap, const __nv_bfloat16* __restrict__ Wp,
    uint32_t base, int m0, int n0, int chunk, int tid)
{
    int co = chunk * 64;
#pragma unroll
    for (int i = 0; i < 4; i++) {       // A: 128 rows x 64 cols, hi+lo
        int f = i * 256 + tid;
        int r = f >> 3, cx = f & 7;
        uint32_t sw = r * 128 + ((cx ^ (r & 7)) << 4);
        const void* gh = Ap + (size_t)(m0 + r) * KROW + co + cx * 8;
        asm volatile("cp.async.cg.shared.global [%0], [%1], 16;" :: "r"(base + sw), "l"(gh));
        const void* gl = Ap + (size_t)(m0 + r) * KROW + 1024 + co + cx * 8;
        asm volatile("cp.async.cg.shared.global [%0], [%1], 16;" :: "r"(base + 16384 + sw), "l"(gl));
    }
#pragma unroll
    for (int i = 0; i < 8; i++) {       // W: 256 rows x 64 cols, hi+lo
        int f = i * 256 + tid;
        int r = f >> 3, cx = f & 7;
        uint32_t sw = r * 128 + ((cx ^ (r & 7)) << 4);
        const void* gh = Wp + (size_t)(n0 + r) * KROW + co + cx * 8;
        asm volatile("cp.async.cg.shared.global [%0], [%1], 16;" :: "r"(base + 32768 + sw), "l"(gh));
        const void* gl = Wp + (size_t)(n0 + r) * KROW + 1024 + co + cx * 8;
        asm volatile("cp.async.cg.shared.global [%0], [%1], 16;" :: "r"(base + 65536 + sw), "l"(gl));
    }
}

__global__ __launch_bounds__(256, 1)
void gemm_mma(const __nv_bfloat16* __restrict__ Ap, const __nv_bfloat16* __restrict__ Wp,
              void* __restrict__ Cv, int mode)
{
    extern __shared__ __align__(128) char smem[];
    uint32_t sb = smem_u32(smem);
    int tid = threadIdx.x;
    int wid = tid >> 5, lane = tid & 31;
    int wm = wid >> 2, wn = wid & 3;        // 2 x 4 warps, warp tile 64x64
    int m0 = blockIdx.y * 128, n0 = blockIdx.x * 256;

    float acc[4][8][4];
#pragma unroll
    for (int i = 0; i < 4; i++)
#pragma unroll
        for (int j = 0; j < 8; j++)
#pragma unroll
            for (int r = 0; r < 4; r++) acc[i][j][r] = 0.f;

    load_chunk(Ap, Wp, sb, m0, n0, 0, tid);
    asm volatile("cp.async.commit_group;" ::: "memory");

    int lm15 = lane & 15, l4 = lane >> 4;

    for (int s = 0; s < NCH; s++) {
        asm volatile("cp.async.wait_group 0;" ::: "memory");
        __syncthreads();
        if (s + 1 < NCH)
            load_chunk(Ap, Wp, sb + ((s + 1) & 1) * STAGE_B, m0, n0, s + 1, tid);
        asm volatile("cp.async.commit_group;" ::: "memory");

        uint32_t B = sb + (s & 1) * STAGE_B;
        uint32_t AH = B, AL = B + 16384, WH = B + 32768, WL = B + 65536;

#pragma unroll
        for (int kk = 0; kk < 4; kk++) {
            int c0 = 2 * kk + l4;
            uint32_t ah[4][4], al[4][4];
#pragma unroll
            for (int i = 0; i < 4; i++) {
                int r = wm * 64 + i * 16 + lm15;
                uint32_t sw = r * 128 + ((c0 ^ (r & 7)) << 4);
                asm volatile("ldmatrix.sync.aligned.m8n8.x4.shared.b16 {%0,%1,%2,%3}, [%4];"
                    : "=r"(ah[i][0]), "=r"(ah[i][1]), "=r"(ah[i][2]), "=r"(ah[i][3]) : "r"(AH + sw));
                asm volatile("ldmatrix.sync.aligned.m8n8.x4.shared.b16 {%0,%1,%2,%3}, [%4];"
                    : "=r"(al[i][0]), "=r"(al[i][1]), "=r"(al[i][2]), "=r"(al[i][3]) : "r"(AL + sw));
            }
#pragma unroll
            for (int g = 0; g < 4; g++) {   // 4 n-groups of 16 cols
                int rW = wn * 64 + g * 16 + lm15;
                uint32_t swW = rW * 128 + ((c0 ^ (rW & 7)) << 4);
                uint32_t bh4[4], bl4[4];
                asm volatile("ldmatrix.sync.aligned.m8n8.x4.shared.b16 {%0,%1,%2,%3}, [%4];"
                    : "=r"(bh4[0]), "=r"(bh4[1]), "=r"(bh4[2]), "=r"(bh4[3]) : "r"(WH + swW));
                asm volatile("ldmatrix.sync.aligned.m8n8.x4.shared.b16 {%0,%1,%2,%3}, [%4];"
                    : "=r"(bl4[0]), "=r"(bl4[1]), "=r"(bl4[2]), "=r"(bl4[3]) : "r"(WL + swW));
#pragma unroll
                for (int j2 = 0; j2 < 2; j2++) {
                    int j = g * 2 + j2;
                    uint32_t bh0 = bh4[j2], bh1 = bh4[j2 + 2];
                    uint32_t bl0 = bl4[j2], bl1 = bl4[j2 + 2];
#pragma unroll
                    for (int i = 0; i < 4; i++) {
                        asm volatile(
                            "mma.sync.aligned.m16n8k16.row.col.f32.bf16.bf16.f32 "
                            "{%0,%1,%2,%3}, {%4,%5,%6,%7}, {%8,%9}, {%0,%1,%2,%3};"
                            : "+f"(acc[i][j][0]), "+f"(acc[i][j][1]),
                              "+f"(acc[i][j][2]), "+f"(acc[i][j][3])
                            : "r"(ah[i][0]), "r"(ah[i][1]), "r"(ah[i][2]), "r"(ah[i][3]),
                              "r"(bh0), "r"(bh1));
                        asm volatile(
                            "mma.sync.aligned.m16n8k16.row.col.f32.bf16.bf16.f32 "
                            "{%0,%1,%2,%3}, {%4,%5,%6,%7}, {%8,%9}, {%0,%1,%2,%3};"
                            : "+f"(acc[i][j][0]), "+f"(acc[i][j][1]),
                              "+f"(acc[i][j][2]), "+f"(acc[i][j][3])
                            : "r"(al[i][0]), "r"(al[i][1]), "r"(al[i][2]), "r"(al[i][3]),
                              "r"(bh0), "r"(bh1));
                        asm volatile(
                            "mma.sync.aligned.m16n8k16.row.col.f32.bf16.bf16.f32 "
                            "{%0,%1,%2,%3}, {%4,%5,%6,%7}, {%8,%9}, {%0,%1,%2,%3};"
                            : "+f"(acc[i][j][0]), "+f"(acc[i][j][1]),
                              "+f"(acc[i][j][2]), "+f"(acc[i][j][3])
                            : "r"(ah[i][0]), "r"(ah[i][1]), "r"(ah[i][2]), "r"(ah[i][3]),
                              "r"(bl0), "r"(bl1));
                    }
                }
            }
        }
    }

    int lr = lane >> 2, lc = (lane & 3) * 2;
#pragma unroll
    for (int i = 0; i < 4; i++) {
#pragma unroll
        for (int j = 0; j < 8; j++) {
            int mA = m0 + wm * 64 + i * 16 + lr;
            int n  = n0 + wn * 64 + j * 8 + lc;
            if (mode == 0) {
                float* C = (float*)Cv;
                *(float2*)(C + (size_t)mA * 1024 + n) = make_float2(acc[i][j][0], acc[i][j][1]);
                *(float2*)(C + (size_t)(mA + 8) * 1024 + n) = make_float2(acc[i][j][2], acc[i][j][3]);
            } else {
                __nv_bfloat16* C = (__nv_bfloat16*)Cv;
                int hI = n >> 6, kk2 = n & 63;
                int bA = mA >> 10, sA = mA & 1023;
#pragma unroll
                for (int half = 0; half < 2; half++) {
                    float x0 = acc[i][j][half * 2], x1 = acc[i][j][half * 2 + 1];
                    __nv_bfloat16 h0 = __float2bfloat16(x0), h1 = __float2bfloat16(x1);
                    uint32_t hp = (uint32_t)__bfloat16_as_ushort(h0) |
                                  ((uint32_t)__bfloat16_as_ushort(h1) << 16);
                    uint32_t lq = pack_bf2(x0 - __bfloat162float(h0), x1 - __bfloat162float(h1));
                    size_t base = ((((size_t)bA * Hc + hI) << 10) + sA + half * 8) * 128 + kk2;
                    *(uint32_t*)(C + base)      = hp;
                    *(uint32_t*)(C + base + 64) = lq;
                }
            }
        }
    }
}

// ---------------------------------------------------------------------------
// Vmean[b,h,d] = mean over s of (vhi+vlo)
// ---------------------------------------------------------------------------
__global__ __launch_bounds__(256) void vmean_kernel(
    const __nv_bfloat16* __restrict__ vs, float* __restrict__ vmean)
{
    __shared__ float smv[64];
    int bh = blockIdx.x;
    int tid = threadIdx.x, lane = tid & 31, wid = tid >> 5;
    if (tid < 64) smv[tid] = 0.f;
    __syncthreads();

    int oct = lane & 15;
    int rsel = lane >> 4;
    float acc[8];
#pragma unroll
    for (int k = 0; k < 8; k++) acc[k] = 0.f;

    const uint4* base = (const uint4*)(vs + (size_t)bh * 1024 * 128);
    for (int s = wid * 2 + rsel; s < 1024; s += 16) {
        uint4 xv = base[s * 16 + oct];
        const __nv_bfloat16* p = (const __nv_bfloat16*)&xv;
#pragma unroll
        for (int k = 0; k < 8; k++) acc[k] += __bfloat162float(p[k]);
    }
#pragma unroll
    for (int k = 0; k < 8; k++) acc[k] += __shfl_xor_sync(0xffffffffu, acc[k], 8);
    if (oct < 8) {
#pragma unroll
        for (int k = 0; k < 8; k++) atomicAdd(&smv[oct * 8 + k], acc[k]);
    }
    __syncthreads();
    if (tid < 64) vmean[bh * 64 + tid] = smv[tid] * (1.0f / 1024.0f);
}

// ---------------------------------------------------------------------------
// FA2-style tensor-core attention (unchanged from R6)
// ---------------------------------------------------------------------------
#define ROWB 272
#define TILEB (128 * ROWB)
#define AT_SMEM (5 * TILEB)

__global__ __launch_bounds__(256, 1)
void attn_mma(const __nv_bfloat16* __restrict__ qs, const __nv_bfloat16* __restrict__ ks,
              const __nv_bfloat16* __restrict__ vs, const int* __restrict__ pm1,
              const int* __restrict__ pm2, const float* __restrict__ vmean,
              __nv_bfloat16* __restrict__ ap)
{
    extern __shared__ __align__(128) char smem[];
    uint32_t sb = smem_u32(smem);
    const uint32_t QS = sb;

    int tid = threadIdx.x, lane = tid & 31, w = tid >> 5;
    int lm15 = lane & 15, l4 = lane >> 4, lr = lane >> 2, lc = (lane & 3) * 2;
    int bh = blockIdx.y, b = bh >> 4, h = bh & 15;
    int i0 = blockIdx.x * 128;
    int p1 = pm1[b], p2 = pm2[b];

    int rw = w * 16;
    int gi0 = i0 + rw + lr, gi1 = gi0 + 8;
    bool fm0 = (gi0 >= p2) || (p1 == 0);
    bool fm1 = (gi1 >= p2) || (p1 == 0);

    int jt_max = 0;
    if (!((i0 >= p2) || (p1 == 0))) {
        int J = min(i0 + 128, p1);
        jt_max = (J + 127) >> 7;
    }

    float po[8][4];
#pragma unroll
    for (int nb = 0; nb < 8; nb++)
#pragma unroll
        for (int r = 0; r < 4; r++) po[nb][r] = 0.f;
    float ls0 = 0.f, ls1 = 0.f;

    if (jt_max > 0) {
        {
            const char* qg = (const char*)(qs + ((size_t)bh * 1024 + i0) * 128);
#pragma unroll
            for (int i = 0; i < 8; i++) {
                int f = i * 256 + tid; int r = f >> 4, c = f & 15;
                asm volatile("cp.async.cg.shared.global [%0], [%1], 16;"
                    :: "r"(QS + r * ROWB + c * 16), "l"(qg + r * 256 + c * 16));
            }
            asm volatile("cp.async.commit_group;" ::: "memory");
        }
        {
            const char* kg = (const char*)(ks + (size_t)bh * 1024 * 128);
            const char* vg = (const char*)(vs + (size_t)bh * 1024 * 128);
            uint32_t KB = sb + TILEB, VB = sb + 2 * TILEB;
#pragma unroll
            for (int i = 0; i < 8; i++) {
                int f = i * 256 + tid; int r = f >> 4, c = f & 15;
                asm volatile("cp.async.cg.shared.global [%0], [%1], 16;"
                    :: "r"(KB + r * ROWB + c * 16), "l"(kg + r * 256 + c * 16));
                asm volatile("cp.async.cg.shared.global [%0], [%1], 16;"
                    :: "r"(VB + r * ROWB + c * 16), "l"(vg + r * 256 + c * 16));
            }
            asm volatile("cp.async.commit_group;" ::: "memory");
        }

        for (int jt = 0; jt < jt_max; jt++) {
            int j0 = jt * 128;
            if (jt + 1 < jt_max) {
                int jn = (jt + 1) & 1;
                uint32_t KB = sb + (1 + 2 * jn) * TILEB;
                uint32_t VB = KB + TILEB;
                const char* kg = (const char*)(ks + ((size_t)bh * 1024 + (jt + 1) * 128) * 128);
                const char* vg = (const char*)(vs + ((size_t)bh * 1024 + (jt + 1) * 128) * 128);
#pragma unroll
                for (int i = 0; i < 8; i++) {
                    int f = i * 256 + tid; int r = f >> 4, c = f & 15;
                    asm volatile("cp.async.cg.shared.global [%0], [%1], 16;"
                        :: "r"(KB + r * ROWB + c * 16), "l"(kg + r * 256 + c * 16));
                    asm volatile("cp.async.cg.shared.global [%0], [%1], 16;"
                        :: "r"(VB + r * ROWB + c * 16), "l"(vg + r * 256 + c * 16));
                }
                asm volatile("cp.async.commit_group;" ::: "memory");
                asm volatile("cp.async.wait_group 1;" ::: "memory");
            } else {
                asm volatile("cp.async.wait_group 0;" ::: "memory");
            }
            __syncthreads();

            uint32_t KS = sb + (1 + 2 * (jt & 1)) * TILEB;
            uint32_t VS = KS + TILEB;

            float sc[16][4];
#pragma unroll
            for (int nb = 0; nb < 16; nb++)
#pragma unroll
                for (int r = 0; r < 4; r++) sc[nb][r] = 0.f;

#pragma unroll
            for (int term = 0; term < 3; term++) {
                int qc = (term == 2) ? 8 : 0;
                int kc = (term == 1) ? 8 : 0;
#pragma unroll
                for (int ks4 = 0; ks4 < 4; ks4++) {
                    uint32_t a[4], bb[8][4];
                    int ca = qc + 2 * ks4 + l4;
                    int cb = kc + 2 * ks4 + l4;
                    asm volatile("ldmatrix.sync.aligned.m8n8.x4.shared.b16 {%0,%1,%2,%3}, [%4];"
                        : "=r"(a[0]), "=r"(a[1]), "=r"(a[2]), "=r"(a[3])
                        : "r"(QS + (rw + lm15) * ROWB + ca * 16));
#pragma unroll
                    for (int g = 0; g < 8; g++) {
                        asm volatile("ldmatrix.sync.aligned.m8n8.x4.shared.b16 {%0,%1,%2,%3}, [%4];"
                            : "=r"(bb[g][0]), "=r"(bb[g][1]), "=r"(bb[g][2]), "=r"(bb[g][3])
                            : "r"(KS + (g * 16 + lm15) * ROWB + cb * 16));
                    }
#pragma unroll
                    for (int nb = 0; nb < 16; nb++) {
                        uint32_t b0 = bb[nb >> 1][nb & 1];
                        uint32_t b1 = bb[nb >> 1][(nb & 1) + 2];
                        asm volatile(
                            "mma.sync.aligned.m16n8k16.row.col.f32.bf16.bf16.f32 "
                            "{%0,%1,%2,%3}, {%4,%5,%6,%7}, {%8,%9}, {%0,%1,%2,%3};"
                            : "+f"(sc[nb][0]), "+f"(sc[nb][1]), "+f"(sc[nb][2]), "+f"(sc[nb][3])
                            : "r"(a[0]), "r"(a[1]), "r"(a[2]), "r"(a[3]), "r"(b0), "r"(b1));
                    }
                }
            }

#pragma unroll
            for (int nb = 0; nb < 16; nb++) {
                int cl = nb * 8 + lc;
                int gj0 = j0 + cl, gj1 = gj0 + 1;
                float v00 = (!fm0 && gj0 <= gi0 && gj0 < p1) ? __expf(sc[nb][0] * 0.125f) : 0.f;
                float v01 = (!fm0 && gj1 <= gi0 && gj1 < p1) ? __expf(sc[nb][1] * 0.125f) : 0.f;
                float v10 = (!fm1 && gj0 <= gi1 && gj0 < p1) ? __expf(sc[nb][2] * 0.125f) : 0.f;
                float v11 = (!fm1 && gj1 <= gi1 && gj1 < p1) ? __expf(sc[nb][3] * 0.125f) : 0.f;
                ls0 += v00 + v01;
                ls1 += v10 + v11;
                sc[nb][0] = v00; sc[nb][1] = v01; sc[nb][2] = v10; sc[nb][3] = v11;
            }

#pragma unroll
            for (int t = 0; t < 8; t++) {
                uint32_t ahi[4], alo[4];
#pragma unroll
                for (int half = 0; half < 2; half++) {
                    float* s4 = sc[2 * t + half];
                    __nv_bfloat16 h0 = __float2bfloat16(s4[0]), h1 = __float2bfloat16(s4[1]);
                    __nv_bfloat16 h2 = __float2bfloat16(s4[2]), h3 = __float2bfloat16(s4[3]);
                    ahi[half * 2]     = (uint32_t)__bfloat16_as_ushort(h0) | ((uint32_t)__bfloat16_as_ushort(h1) << 16);
                    ahi[half * 2 + 1] = (uint32_t)__bfloat16_as_ushort(h2) | ((uint32_t)__bfloat16_as_ushort(h3) << 16);
                    alo[half * 2]     = pack_bf2(s4[0] - __bfloat162float(h0), s4[1] - __bfloat162float(h1));
                    alo[half * 2 + 1] = pack_bf2(s4[2] - __bfloat162float(h2), s4[3] - __bfloat162float(h3));
                }
                uint32_t af_hi[4] = { ahi[0], ahi[1], ahi[2], ahi[3] };
                uint32_t af_lo[4] = { alo[0], alo[1], alo[2], alo[3] };

                uint32_t bth[4][4], btl[4][4];
#pragma unroll
                for (int db = 0; db < 4; db++) {
                    int rv = t * 16 + lm15;
                    asm volatile("ldmatrix.sync.aligned.m8n8.x4.trans.shared.b16 {%0,%1,%2,%3}, [%4];"
                        : "=r"(bth[db][0]), "=r"(bth[db][1]), "=r"(bth[db][2]), "=r"(bth[db][3])
                        : "r"(VS + rv * ROWB + (db * 2 + l4) * 16));
                    asm volatile("ldmatrix.sync.aligned.m8n8.x4.trans.shared.b16 {%0,%1,%2,%3}, [%4];"
                        : "=r"(btl[db][0]), "=r"(btl[db][1]), "=r"(btl[db][2]), "=r"(btl[db][3])
                        : "r"(VS + rv * ROWB + (8 + db * 2 + l4) * 16));
                }
#pragma unroll
                for (int db = 0; db < 4; db++)
#pragma unroll
                    for (int nf = 0; nf < 2; nf++) {
                        int nb = db * 2 + nf;
                        asm volatile(
                            "mma.sync.aligned.m16n8k16.row.col.f32.bf16.bf16.f32 "
                            "{%0,%1,%2,%3}, {%4,%5,%6,%7}, {%8,%9}, {%0,%1,%2,%3};"
                            : "+f"(po[nb][0]), "+f"(po[nb][1]), "+f"(po[nb][2]), "+f"(po[nb][3])
                            : "r"(af_hi[0]), "r"(af_hi[1]), "r"(af_hi[2]), "r"(af_hi[3]),
                              "r"(bth[db][nf * 2]), "r"(bth[db][nf * 2 + 1]));
                        asm volatile(
                            "mma.sync.aligned.m16n8k16.row.col.f32.bf16.bf16.f32 "
                            "{%0,%1,%2,%3}, {%4,%5,%6,%7}, {%8,%9}, {%0,%1,%2,%3};"
                            : "+f"(po[nb][0]), "+f"(po[nb][1]), "+f"(po[nb][2]), "+f"(po[nb][3])
                            : "r"(af_hi[0]), "r"(af_hi[1]), "r"(af_hi[2]), "r"(af_hi[3]),
                              "r"(btl[db][nf * 2]), "r"(btl[db][nf * 2 + 1]));
                        asm volatile(
                            "mma.sync.aligned.m16n8k16.row.col.f32.bf16.bf16.f32 "
                            "{%0,%1,%2,%3}, {%4,%5,%6,%7}, {%8,%9}, {%0,%1,%2,%3};"
                            : "+f"(po[nb][0]), "+f"(po[nb][1]), "+f"(po[nb][2]), "+f"(po[nb][3])
                            : "r"(af_lo[0]), "r"(af_lo[1]), "r"(af_lo[2]), "r"(af_lo[3]),
                              "r"(bth[db][nf * 2]), "r"(bth[db][nf * 2 + 1]));
                    }
            }
            __syncthreads();
        }
    }

    ls0 += __shfl_xor_sync(0xffffffffu, ls0, 1);
    ls0 += __shfl_xor_sync(0xffffffffu, ls0, 2);
    ls1 += __shfl_xor_sync(0xffffffffu, ls1, 1);
    ls1 += __shfl_xor_sync(0xffffffffu, ls1, 2);
    float inv0 = fm0 ? 0.f : 1.0f / ls0;
    float inv1 = fm1 ? 0.f : 1.0f / ls1;

    size_t mr0 = ((size_t)b * 1024 + (i0 + rw + lr)) * (size_t)KROW;
    size_t mr1 = ((size_t)b * 1024 + (i0 + rw + lr + 8)) * (size_t)KROW;
#pragma unroll
    for (int nb = 0; nb < 8; nb++) {
        int d = nb * 8 + lc;
        int col = h * 64 + d;
        float x0, x1, y0, y1;
        if (fm0) { x0 = vmean[bh * 64 + d]; x1 = vmean[bh * 64 + d + 1]; }
        else     { x0 = po[nb][0] * inv0;   x1 = po[nb][1] * inv0; }
        if (fm1) { y0 = vmean[bh * 64 + d]; y1 = vmean[bh * 64 + d + 1]; }
        else     { y0 = po[nb][2] * inv1;   y1 = po[nb][3] * inv1; }

        __nv_bfloat16 hx0 = __float2bfloat16(x0), hx1 = __float2bfloat16(x1);
        uint32_t hp0 = (uint32_t)__bfloat16_as_ushort(hx0) | ((uint32_t)__bfloat16_as_ushort(hx1) << 16);
        uint32_t lq0 = pack_bf2(x0 - __bfloat162float(hx0), x1 - __bfloat162float(hx1));
        __nv_bfloat16 hy0 = __float2bfloat16(y0), hy1 = __float2bfloat16(y1);
        uint32_t hp1 = (uint32_t)__bfloat16_as_ushort(hy0) | ((uint32_t)__bfloat16_as_ushort(hy1) << 16);
        uint32_t lq1 = pack_bf2(y0 - __bfloat162float(hy0), y1 - __bfloat162float(hy1));

        *(uint32_t*)(ap + mr0 + col)        = hp0;
        *(uint32_t*)(ap + mr0 + col + 1024) = lq0;
        *(uint32_t*)(ap + mr1 + col)        = hp1;
        *(uint32_t*)(ap + mr1 + col + 1024) = lq1;
    }
}

// ---------------------------------------------------------------------------
extern "C" void kernel_launch(void* const* d_in, const int* in_sizes, int n_in,
                              void* d_out, int out_size)
{
    const float* q   = (const float*)d_in[0];
    const float* k   = (const float*)d_in[1];
    const float* v   = (const float*)d_in[2];
    const int*   pm1 = (const int*)d_in[3];
    const int*   pm2 = (const int*)d_in[4];
    const float* Wq  = (const float*)d_in[5];
    const float* Wk  = (const float*)d_in[6];
    const float* Wv  = (const float*)d_in[7];
    const float* Wo  = (const float*)d_in[8];
    float* out = (float*)d_out;

    __nv_bfloat16 *qs, *ksp, *vsp, *ap, *wp;
    float* vmean;
    cudaGetSymbolAddress((void**)&qs,    g_qs);
    cudaGetSymbolAddress((void**)&ksp,   g_ks);
    cudaGetSymbolAddress((void**)&vsp,   g_vs);
    cudaGetSymbolAddress((void**)&ap,    g_ap);
    cudaGetSymbolAddress((void**)&wp,    g_wp);
    cudaGetSymbolAddress((void**)&vmean, g_vmean);

    cudaFuncSetAttribute(gemm_mma,
        cudaFuncAttributeMaxDynamicSharedMemorySize, GEMM_SMEM);
    cudaFuncSetAttribute(attn_mma,
        cudaFuncAttributeMaxDynamicSharedMemorySize, AT_SMEM);

    const int A8 = Mrows * 128;                    // 1M threads (8 floats each)
    const size_t WSEC = (size_t)Dc * KROW;         // per-W section in g_wp
    dim3 gg(Dc / 256, Mrows / 128);                // (4, 64)

    // All 4 weight splits in one launch
    conv_w_all<<<dim3(512, 4), 256>>>(Wq, Wk, Wv, Wo, wp);

    conv_split8<<<A8 / 256, 256>>>(q, ap, A8);
    gemm_mma<<<gg, 256, GEMM_SMEM>>>(ap, wp + 0 * WSEC, (void*)qs, 2);

    conv_split8<<<A8 / 256, 256>>>(k, ap, A8);
    gemm_mma<<<gg, 256, GEMM_SMEM>>>(ap, wp + 1 * WSEC, (void*)ksp, 2);

    conv_split8<<<A8 / 256, 256>>>(v, ap, A8);
    gemm_mma<<<gg, 256, GEMM_SMEM>>>(ap, wp + 2 * WSEC, (void*)vsp, 2);

    vmean_kernel<<<Bc * Hc, 256>>>(vsp, vmean);

    attn_mma<<<dim3(Sc / 128, Bc * Hc), 256, AT_SMEM>>>(qs, ksp, vsp, pm1, pm2, vmean, ap);

    gemm_mma<<<gg, 256, GEMM_SMEM>>>(ap, wp + 3 * WSEC, (void*)out, 0);
}

// round 8
// speedup vs baseline: 4.4748x; 1.0134x over previous
#include <cuda_runtime.h>
#include <cuda_bf16.h>
#include <math.h>
#include <stdint.h>

// Problem constants
#define Bc   8
#define Sc   1024
#define Dc   1024
#define Hc   16
#define Mrows (Bc*Sc)      // 8192
#define KROW 2048          // compact split: [hi(1024) | lo(1024)]
#define NCH  16            // 16 K-chunks of 64
#define ASEC ((size_t)Mrows*KROW)   // per-input A section
#define WSEC ((size_t)Dc*KROW)      // per-W section

// ---------------- scratch (device globals: allocation-free) ----------------
__device__ __nv_bfloat16 g_qs[(size_t)Bc*Hc*Sc*128];  // [B,H,S,128]=[hi64|lo64]
__device__ __nv_bfloat16 g_ks[(size_t)Bc*Hc*Sc*128];
__device__ __nv_bfloat16 g_vs[(size_t)Bc*Hc*Sc*128];
__device__ __nv_bfloat16 g_ap[3*ASEC];                // 96 MB (q,k,v splits; sec0 reused by attn out)
__device__ __nv_bfloat16 g_wp[4*WSEC];                // 16 MB (Wq,Wk,Wv,Wo)
__device__ float g_vmean[Bc*Hc*64];

__device__ __forceinline__ uint32_t smem_u32(const void* p) {
    uint32_t a;
    asm("{ .reg .u64 t; cvta.to.shared.u64 t, %1; cvt.u32.u64 %0, t; }"
        : "=r"(a) : "l"(p));
    return a;
}

__device__ __forceinline__ uint32_t pack_bf2(float a, float b) {
    __nv_bfloat16 ha = __float2bfloat16(a), hb = __float2bfloat16(b);
    return (uint32_t)__bfloat16_as_ushort(ha) | ((uint32_t)__bfloat16_as_ushort(hb) << 16);
}

// ---------------------------------------------------------------------------
// fp32 -> bf16 compact split, 8 floats/thread; 3 inputs in one launch.
// ---------------------------------------------------------------------------
__device__ __forceinline__ void conv8_core(const float* __restrict__ src,
                                           __nv_bfloat16* __restrict__ dst_hi,
                                           __nv_bfloat16* __restrict__ dst_lo)
{
    float4 x0 = *(const float4*)src;
    float4 x1 = *(const float4*)(src + 4);
    __nv_bfloat16 h0 = __float2bfloat16(x0.x), h1 = __float2bfloat16(x0.y);
    __nv_bfloat16 h2 = __float2bfloat16(x0.z), h3 = __float2bfloat16(x0.w);
    __nv_bfloat16 h4 = __float2bfloat16(x1.x), h5 = __float2bfloat16(x1.y);
    __nv_bfloat16 h6 = __float2bfloat16(x1.z), h7 = __float2bfloat16(x1.w);
    uint4 hv, lv;
    hv.x = (uint32_t)__bfloat16_as_ushort(h0) | ((uint32_t)__bfloat16_as_ushort(h1) << 16);
    hv.y = (uint32_t)__bfloat16_as_ushort(h2) | ((uint32_t)__bfloat16_as_ushort(h3) << 16);
    hv.z = (uint32_t)__bfloat16_as_ushort(h4) | ((uint32_t)__bfloat16_as_ushort(h5) << 16);
    hv.w = (uint32_t)__bfloat16_as_ushort(h6) | ((uint32_t)__bfloat16_as_ushort(h7) << 16);
    lv.x = pack_bf2(x0.x - __bfloat162float(h0), x0.y - __bfloat162float(h1));
    lv.y = pack_bf2(x0.z - __bfloat162float(h2), x0.w - __bfloat162float(h3));
    lv.z = pack_bf2(x1.x - __bfloat162float(h4), x1.y - __bfloat162float(h5));
    lv.w = pack_bf2(x1.z - __bfloat162float(h6), x1.w - __bfloat162float(h7));
    *(uint4*)dst_hi = hv;
    *(uint4*)dst_lo = lv;
}

__global__ __launch_bounds__(256) void conv_a3(
    const float* __restrict__ q, const float* __restrict__ k,
    const float* __restrict__ v, __nv_bfloat16* __restrict__ Y)
{
    const float* X = (blockIdx.y == 0) ? q : (blockIdx.y == 1) ? k : v;
    int i = blockIdx.x * 256 + threadIdx.x;     // Mrows*128 threads
    int r = i >> 7;
    int c8 = (i & 127) << 3;
    size_t base = (size_t)blockIdx.y * ASEC + (size_t)r * KROW;
    conv8_core(X + (size_t)r * 1024 + c8, Y + base + c8, Y + base + 1024 + c8);
}

__global__ __launch_bounds__(256) void conv_w_all(
    const float* __restrict__ W0, const float* __restrict__ W1,
    const float* __restrict__ W2, const float* __restrict__ W3,
    __nv_bfloat16* __restrict__ Y)
{
    const float* X = (blockIdx.y == 0) ? W0 : (blockIdx.y == 1) ? W1
                   : (blockIdx.y == 2) ? W2 : W3;
    int i = blockIdx.x * 256 + threadIdx.x;
    int r = i >> 7;
    int c8 = (i & 127) << 3;
    size_t base = (size_t)blockIdx.y * WSEC + (size_t)r * KROW;
    conv8_core(X + (size_t)r * 1024 + c8, Y + base + c8, Y + base + 1024 + c8);
}

// ---------------------------------------------------------------------------
// Chunk-fused bf16 split GEMM (CTA 128x256, double-buffered 2x96KB).
// blockIdx.z selects the (A-section, W-section, output) triple.
// mode 0: C fp32 [M,1024]; mode 2: C bf16 split-head [B,H,S,128]
// ---------------------------------------------------------------------------
#define STAGE_B 98304
#define GEMM_SMEM (2 * STAGE_B)

__device__ __forceinline__ void load_chunk(
    const __nv_bfloat16* __restrict__ Ap, const __nv_bfloat16* __restrict__ Wp,
    uint32_t base, int m0, int n0, int chunk, int tid)
{
    int co = chunk * 64;
#pragma unroll
    for (int i = 0; i < 4; i++) {
        int f = i * 256 + tid;
        int r = f >> 3, cx = f & 7;
        uint32_t sw = r * 128 + ((cx ^ (r & 7)) << 4);
        const void* gh = Ap + (size_t)(m0 + r) * KROW + co + cx * 8;
        asm volatile("cp.async.cg.shared.global [%0], [%1], 16;" :: "r"(base + sw), "l"(gh));
        const void* gl = Ap + (size_t)(m0 + r) * KROW + 1024 + co + cx * 8;
        asm volatile("cp.async.cg.shared.global [%0], [%1], 16;" :: "r"(base + 16384 + sw), "l"(gl));
    }
#pragma unroll
    for (int i = 0; i < 8; i++) {
        int f = i * 256 + tid;
        int r = f >> 3, cx = f & 7;
        uint32_t sw = r * 128 + ((cx ^ (r & 7)) << 4);
        const void* gh = Wp + (size_t)(n0 + r) * KROW + co + cx * 8;
        asm volatile("cp.async.cg.shared.global [%0], [%1], 16;" :: "r"(base + 32768 + sw), "l"(gh));
        const void* gl = Wp + (size_t)(n0 + r) * KROW + 1024 + co + cx * 8;
        asm volatile("cp.async.cg.shared.global [%0], [%1], 16;" :: "r"(base + 65536 + sw), "l"(gl));
    }
}

__global__ __launch_bounds__(256, 1)
void gemm_mma(const __nv_bfloat16* __restrict__ ApB, const __nv_bfloat16* __restrict__ WpB,
              void* C0, void* C1, void* C2, int mode)
{
    extern __shared__ __align__(128) char smem[];
    uint32_t sb = smem_u32(smem);
    int tid = threadIdx.x;
    int wid = tid >> 5, lane = tid & 31;
    int wm = wid >> 2, wn = wid & 3;
    int m0 = blockIdx.y * 128, n0 = blockIdx.x * 256;
    int z = blockIdx.z;
    const __nv_bfloat16* Ap = ApB + (size_t)z * ASEC;
    const __nv_bfloat16* Wp = WpB + (size_t)z * WSEC;
    void* Cv = (z == 0) ? C0 : (z == 1) ? C1 : C2;

    float acc[4][8][4];
#pragma unroll
    for (int i = 0; i < 4; i++)
#pragma unroll
        for (int j = 0; j < 8; j++)
#pragma unroll
            for (int r = 0; r < 4; r++) acc[i][j][r] = 0.f;

    load_chunk(Ap, Wp, sb, m0, n0, 0, tid);
    asm volatile("cp.async.commit_group;" ::: "memory");

    int lm15 = lane & 15, l4 = lane >> 4;

    for (int s = 0; s < NCH; s++) {
        asm volatile("cp.async.wait_group 0;" ::: "memory");
        __syncthreads();
        if (s + 1 < NCH)
            load_chunk(Ap, Wp, sb + ((s + 1) & 1) * STAGE_B, m0, n0, s + 1, tid);
        asm volatile("cp.async.commit_group;" ::: "memory");

        uint32_t B = sb + (s & 1) * STAGE_B;
        uint32_t AH = B, AL = B + 16384, WH = B + 32768, WL = B + 65536;

#pragma unroll
        for (int kk = 0; kk < 4; kk++) {
            int c0 = 2 * kk + l4;
            uint32_t ah[4][4], al[4][4];
#pragma unroll
            for (int i = 0; i < 4; i++) {
                int r = wm * 64 + i * 16 + lm15;
                uint32_t sw = r * 128 + ((c0 ^ (r & 7)) << 4);
                asm volatile("ldmatrix.sync.aligned.m8n8.x4.shared.b16 {%0,%1,%2,%3}, [%4];"
                    : "=r"(ah[i][0]), "=r"(ah[i][1]), "=r"(ah[i][2]), "=r"(ah[i][3]) : "r"(AH + sw));
                asm volatile("ldmatrix.sync.aligned.m8n8.x4.shared.b16 {%0,%1,%2,%3}, [%4];"
                    : "=r"(al[i][0]), "=r"(al[i][1]), "=r"(al[i][2]), "=r"(al[i][3]) : "r"(AL + sw));
            }
#pragma unroll
            for (int g = 0; g < 4; g++) {
                int rW = wn * 64 + g * 16 + lm15;
                uint32_t swW = rW * 128 + ((c0 ^ (rW & 7)) << 4);
                uint32_t bh4[4], bl4[4];
                asm volatile("ldmatrix.sync.aligned.m8n8.x4.shared.b16 {%0,%1,%2,%3}, [%4];"
                    : "=r"(bh4[0]), "=r"(bh4[1]), "=r"(bh4[2]), "=r"(bh4[3]) : "r"(WH + swW));
                asm volatile("ldmatrix.sync.aligned.m8n8.x4.shared.b16 {%0,%1,%2,%3}, [%4];"
                    : "=r"(bl4[0]), "=r"(bl4[1]), "=r"(bl4[2]), "=r"(bl4[3]) : "r"(WL + swW));
#pragma unroll
                for (int j2 = 0; j2 < 2; j2++) {
                    int j = g * 2 + j2;
                    uint32_t bh0 = bh4[j2], bh1 = bh4[j2 + 2];
                    uint32_t bl0 = bl4[j2], bl1 = bl4[j2 + 2];
#pragma unroll
                    for (int i = 0; i < 4; i++) {
                        asm volatile(
                            "mma.sync.aligned.m16n8k16.row.col.f32.bf16.bf16.f32 "
                            "{%0,%1,%2,%3}, {%4,%5,%6,%7}, {%8,%9}, {%0,%1,%2,%3};"
                            : "+f"(acc[i][j][0]), "+f"(acc[i][j][1]),
                              "+f"(acc[i][j][2]), "+f"(acc[i][j][3])
                            : "r"(ah[i][0]), "r"(ah[i][1]), "r"(ah[i][2]), "r"(ah[i][3]),
                              "r"(bh0), "r"(bh1));
                        asm volatile(
                            "mma.sync.aligned.m16n8k16.row.col.f32.bf16.bf16.f32 "
                            "{%0,%1,%2,%3}, {%4,%5,%6,%7}, {%8,%9}, {%0,%1,%2,%3};"
                            : "+f"(acc[i][j][0]), "+f"(acc[i][j][1]),
                              "+f"(acc[i][j][2]), "+f"(acc[i][j][3])
                            : "r"(al[i][0]), "r"(al[i][1]), "r"(al[i][2]), "r"(al[i][3]),
                              "r"(bh0), "r"(bh1));
                        asm volatile(
                            "mma.sync.aligned.m16n8k16.row.col.f32.bf16.bf16.f32 "
                            "{%0,%1,%2,%3}, {%4,%5,%6,%7}, {%8,%9}, {%0,%1,%2,%3};"
                            : "+f"(acc[i][j][0]), "+f"(acc[i][j][1]),
                              "+f"(acc[i][j][2]), "+f"(acc[i][j][3])
                            : "r"(ah[i][0]), "r"(ah[i][1]), "r"(ah[i][2]), "r"(ah[i][3]),
                              "r"(bl0), "r"(bl1));
                    }
                }
            }
        }
    }

    int lr = lane >> 2, lc = (lane & 3) * 2;
#pragma unroll
    for (int i = 0; i < 4; i++) {
#pragma unroll
        for (int j = 0; j < 8; j++) {
            int mA = m0 + wm * 64 + i * 16 + lr;
            int n  = n0 + wn * 64 + j * 8 + lc;
            if (mode == 0) {
                float* C = (float*)Cv;
                *(float2*)(C + (size_t)mA * 1024 + n) = make_float2(acc[i][j][0], acc[i][j][1]);
                *(float2*)(C + (size_t)(mA + 8) * 1024 + n) = make_float2(acc[i][j][2], acc[i][j][3]);
            } else {
                __nv_bfloat16* C = (__nv_bfloat16*)Cv;
                int hI = n >> 6, kk2 = n & 63;
                int bA = mA >> 10, sA = mA & 1023;
#pragma unroll
                for (int half = 0; half < 2; half++) {
                    float x0 = acc[i][j][half * 2], x1 = acc[i][j][half * 2 + 1];
                    __nv_bfloat16 h0 = __float2bfloat16(x0), h1 = __float2bfloat16(x1);
                    uint32_t hp = (uint32_t)__bfloat16_as_ushort(h0) |
                                  ((uint32_t)__bfloat16_as_ushort(h1) << 16);
                    uint32_t lq = pack_bf2(x0 - __bfloat162float(h0), x1 - __bfloat162float(h1));
                    size_t base = ((((size_t)bA * Hc + hI) << 10) + sA + half * 8) * 128 + kk2;
                    *(uint32_t*)(C + base)      = hp;
                    *(uint32_t*)(C + base + 64) = lq;
                }
            }
        }
    }
}

// ---------------------------------------------------------------------------
// Vmean[b,h,d] = mean over s of (vhi+vlo)
// ---------------------------------------------------------------------------
__global__ __launch_bounds__(256) void vmean_kernel(
    const __nv_bfloat16* __restrict__ vs, float* __restrict__ vmean)
{
    __shared__ float smv[64];
    int bh = blockIdx.x;
    int tid = threadIdx.x, lane = tid & 31, wid = tid >> 5;
    if (tid < 64) smv[tid] = 0.f;
    __syncthreads();

    int oct = lane & 15;
    int rsel = lane >> 4;
    float acc[8];
#pragma unroll
    for (int k = 0; k < 8; k++) acc[k] = 0.f;

    const uint4* base = (const uint4*)(vs + (size_t)bh * 1024 * 128);
    for (int s = wid * 2 + rsel; s < 1024; s += 16) {
        uint4 xv = base[s * 16 + oct];
        const __nv_bfloat16* p = (const __nv_bfloat16*)&xv;
#pragma unroll
        for (int k = 0; k < 8; k++) acc[k] += __bfloat162float(p[k]);
    }
#pragma unroll
    for (int k = 0; k < 8; k++) acc[k] += __shfl_xor_sync(0xffffffffu, acc[k], 8);
    if (oct < 8) {
#pragma unroll
        for (int k = 0; k < 8; k++) atomicAdd(&smv[oct * 8 + k], acc[k]);
    }
    __syncthreads();
    if (tid < 64) vmean[bh * 64 + tid] = smv[tid] * (1.0f / 1024.0f);
}

// ---------------------------------------------------------------------------
// FA2-style tensor-core attention; S-phase shares Q/K fragments across terms.
// ---------------------------------------------------------------------------
#define ROWB 272
#define TILEB (128 * ROWB)
#define AT_SMEM (5 * TILEB)

__global__ __launch_bounds__(256, 1)
void attn_mma(const __nv_bfloat16* __restrict__ qs, const __nv_bfloat16* __restrict__ ks,
              const __nv_bfloat16* __restrict__ vs, const int* __restrict__ pm1,
              const int* __restrict__ pm2, const float* __restrict__ vmean,
              __nv_bfloat16* __restrict__ ap)
{
    extern __shared__ __align__(128) char smem[];
    uint32_t sb = smem_u32(smem);
    const uint32_t QS = sb;

    int tid = threadIdx.x, lane = tid & 31, w = tid >> 5;
    int lm15 = lane & 15, l4 = lane >> 4, lr = lane >> 2, lc = (lane & 3) * 2;
    int bh = blockIdx.y, b = bh >> 4, h = bh & 15;
    int i0 = blockIdx.x * 128;
    int p1 = pm1[b], p2 = pm2[b];

    int rw = w * 16;
    int gi0 = i0 + rw + lr, gi1 = gi0 + 8;
    bool fm0 = (gi0 >= p2) || (p1 == 0);
    bool fm1 = (gi1 >= p2) || (p1 == 0);

    int jt_max = 0;
    if (!((i0 >= p2) || (p1 == 0))) {
        int J = min(i0 + 128, p1);
        jt_max = (J + 127) >> 7;
    }

    float po[8][4];
#pragma unroll
    for (int nb = 0; nb < 8; nb++)
#pragma unroll
        for (int r = 0; r < 4; r++) po[nb][r] = 0.f;
    float ls0 = 0.f, ls1 = 0.f;

    if (jt_max > 0) {
        {
            const char* qg = (const char*)(qs + ((size_t)bh * 1024 + i0) * 128);
#pragma unroll
            for (int i = 0; i < 8; i++) {
                int f = i * 256 + tid; int r = f >> 4, c = f & 15;
                asm volatile("cp.async.cg.shared.global [%0], [%1], 16;"
                    :: "r"(QS + r * ROWB + c * 16), "l"(qg + r * 256 + c * 16));
            }
            asm volatile("cp.async.commit_group;" ::: "memory");
        }
        {
            const char* kg = (const char*)(ks + (size_t)bh * 1024 * 128);
            const char* vg = (const char*)(vs + (size_t)bh * 1024 * 128);
            uint32_t KB = sb + TILEB, VB = sb + 2 * TILEB;
#pragma unroll
            for (int i = 0; i < 8; i++) {
                int f = i * 256 + tid; int r = f >> 4, c = f & 15;
                asm volatile("cp.async.cg.shared.global [%0], [%1], 16;"
                    :: "r"(KB + r * ROWB + c * 16), "l"(kg + r * 256 + c * 16));
                asm volatile("cp.async.cg.shared.global [%0], [%1], 16;"
                    :: "r"(VB + r * ROWB + c * 16), "l"(vg + r * 256 + c * 16));
            }
            asm volatile("cp.async.commit_group;" ::: "memory");
        }

        for (int jt = 0; jt < jt_max; jt++) {
            int j0 = jt * 128;
            if (jt + 1 < jt_max) {
                int jn = (jt + 1) & 1;
                uint32_t KB = sb + (1 + 2 * jn) * TILEB;
                uint32_t VB = KB + TILEB;
                const char* kg = (const char*)(ks + ((size_t)bh * 1024 + (jt + 1) * 128) * 128);
                const char* vg = (const char*)(vs + ((size_t)bh * 1024 + (jt + 1) * 128) * 128);
#pragma unroll
                for (int i = 0; i < 8; i++) {
                    int f = i * 256 + tid; int r = f >> 4, c = f & 15;
                    asm volatile("cp.async.cg.shared.global [%0], [%1], 16;"
                        :: "r"(KB + r * ROWB + c * 16), "l"(kg + r * 256 + c * 16));
                    asm volatile("cp.async.cg.shared.global [%0], [%1], 16;"
                        :: "r"(VB + r * ROWB + c * 16), "l"(vg + r * 256 + c * 16));
                }
                asm volatile("cp.async.commit_group;" ::: "memory");
                asm volatile("cp.async.wait_group 1;" ::: "memory");
            } else {
                asm volatile("cp.async.wait_group 0;" ::: "memory");
            }
            __syncthreads();

            uint32_t KS = sb + (1 + 2 * (jt & 1)) * TILEB;
            uint32_t VS = KS + TILEB;

            float sc[16][4];
#pragma unroll
            for (int nb = 0; nb < 16; nb++)
#pragma unroll
                for (int r = 0; r < 4; r++) sc[nb][r] = 0.f;

            // ---- S = Qhi*Khi + Qhi*Klo + Qlo*Khi, frags shared across terms ----
#pragma unroll
            for (int ks4 = 0; ks4 < 4; ks4++) {
                uint32_t a_hi[4], a_lo[4], bb_h[8][4], bb_l[8][4];
                int ch = 2 * ks4 + l4, cl = 8 + 2 * ks4 + l4;
                asm volatile("ldmatrix.sync.aligned.m8n8.x4.shared.b16 {%0,%1,%2,%3}, [%4];"
                    : "=r"(a_hi[0]), "=r"(a_hi[1]), "=r"(a_hi[2]), "=r"(a_hi[3])
                    : "r"(QS + (rw + lm15) * ROWB + ch * 16));
                asm volatile("ldmatrix.sync.aligned.m8n8.x4.shared.b16 {%0,%1,%2,%3}, [%4];"
                    : "=r"(a_lo[0]), "=r"(a_lo[1]), "=r"(a_lo[2]), "=r"(a_lo[3])
                    : "r"(QS + (rw + lm15) * ROWB + cl * 16));
#pragma unroll
                for (int g = 0; g < 8; g++) {
                    asm volatile("ldmatrix.sync.aligned.m8n8.x4.shared.b16 {%0,%1,%2,%3}, [%4];"
                        : "=r"(bb_h[g][0]), "=r"(bb_h[g][1]), "=r"(bb_h[g][2]), "=r"(bb_h[g][3])
                        : "r"(KS + (g * 16 + lm15) * ROWB + ch * 16));
                    asm volatile("ldmatrix.sync.aligned.m8n8.x4.shared.b16 {%0,%1,%2,%3}, [%4];"
                        : "=r"(bb_l[g][0]), "=r"(bb_l[g][1]), "=r"(bb_l[g][2]), "=r"(bb_l[g][3])
                        : "r"(KS + (g * 16 + lm15) * ROWB + cl * 16));
                }
#pragma unroll
                for (int nb = 0; nb < 16; nb++) {
                    uint32_t bh0 = bb_h[nb >> 1][nb & 1], bh1 = bb_h[nb >> 1][(nb & 1) + 2];
                    uint32_t bl0 = bb_l[nb >> 1][nb & 1], bl1 = bb_l[nb >> 1][(nb & 1) + 2];
                    asm volatile(
                        "mma.sync.aligned.m16n8k16.row.col.f32.bf16.bf16.f32 "
                        "{%0,%1,%2,%3}, {%4,%5,%6,%7}, {%8,%9}, {%0,%1,%2,%3};"
                        : "+f"(sc[nb][0]), "+f"(sc[nb][1]), "+f"(sc[nb][2]), "+f"(sc[nb][3])
                        : "r"(a_hi[0]), "r"(a_hi[1]), "r"(a_hi[2]), "r"(a_hi[3]), "r"(bh0), "r"(bh1));
                    asm volatile(
                        "mma.sync.aligned.m16n8k16.row.col.f32.bf16.bf16.f32 "
                        "{%0,%1,%2,%3}, {%4,%5,%6,%7}, {%8,%9}, {%0,%1,%2,%3};"
                        : "+f"(sc[nb][0]), "+f"(sc[nb][1]), "+f"(sc[nb][2]), "+f"(sc[nb][3])
                        : "r"(a_hi[0]), "r"(a_hi[1]), "r"(a_hi[2]), "r"(a_hi[3]), "r"(bl0), "r"(bl1));
                    asm volatile(
                        "mma.sync.aligned.m16n8k16.row.col.f32.bf16.bf16.f32 "
                        "{%0,%1,%2,%3}, {%4,%5,%6,%7}, {%8,%9}, {%0,%1,%2,%3};"
                        : "+f"(sc[nb][0]), "+f"(sc[nb][1]), "+f"(sc[nb][2]), "+f"(sc[nb][3])
                        : "r"(a_lo[0]), "r"(a_lo[1]), "r"(a_lo[2]), "r"(a_lo[3]), "r"(bh0), "r"(bh1));
                }
            }

#pragma unroll
            for (int nb = 0; nb < 16; nb++) {
                int cl2 = nb * 8 + lc;
                int gj0 = j0 + cl2, gj1 = gj0 + 1;
                float v00 = (!fm0 && gj0 <= gi0 && gj0 < p1) ? __expf(sc[nb][0] * 0.125f) : 0.f;
                float v01 = (!fm0 && gj1 <= gi0 && gj1 < p1) ? __expf(sc[nb][1] * 0.125f) : 0.f;
                float v10 = (!fm1 && gj0 <= gi1 && gj0 < p1) ? __expf(sc[nb][2] * 0.125f) : 0.f;
                float v11 = (!fm1 && gj1 <= gi1 && gj1 < p1) ? __expf(sc[nb][3] * 0.125f) : 0.f;
                ls0 += v00 + v01;
                ls1 += v10 + v11;
                sc[nb][0] = v00; sc[nb][1] = v01; sc[nb][2] = v10; sc[nb][3] = v11;
            }

#pragma unroll
            for (int t = 0; t < 8; t++) {
                uint32_t ahi[4], alo[4];
#pragma unroll
                for (int half = 0; half < 2; half++) {
                    float* s4 = sc[2 * t + half];
                    __nv_bfloat16 h0 = __float2bfloat16(s4[0]), h1 = __float2bfloat16(s4[1]);
                    __nv_bfloat16 h2 = __float2bfloat16(s4[2]), h3 = __float2bfloat16(s4[3]);
                    ahi[half * 2]     = (uint32_t)__bfloat16_as_ushort(h0) | ((uint32_t)__bfloat16_as_ushort(h1) << 16);
                    ahi[half * 2 + 1] = (uint32_t)__bfloat16_as_ushort(h2) | ((uint32_t)__bfloat16_as_ushort(h3) << 16);
                    alo[half * 2]     = pack_bf2(s4[0] - __bfloat162float(h0), s4[1] - __bfloat162float(h1));
                    alo[half * 2 + 1] = pack_bf2(s4[2] - __bfloat162float(h2), s4[3] - __bfloat162float(h3));
                }
                uint32_t af_hi[4] = { ahi[0], ahi[1], ahi[2], ahi[3] };
                uint32_t af_lo[4] = { alo[0], alo[1], alo[2], alo[3] };

                uint32_t bth[4][4], btl[4][4];
#pragma unroll
                for (int db = 0; db < 4; db++) {
                    int rv = t * 16 + lm15;
                    asm volatile("ldmatrix.sync.aligned.m8n8.x4.trans.shared.b16 {%0,%1,%2,%3}, [%4];"
                        : "=r"(bth[db][0]), "=r"(bth[db][1]), "=r"(bth[db][2]), "=r"(bth[db][3])
                        : "r"(VS + rv * ROWB + (db * 2 + l4) * 16));
                    asm volatile("ldmatrix.sync.aligned.m8n8.x4.trans.shared.b16 {%0,%1,%2,%3}, [%4];"
                        : "=r"(btl[db][0]), "=r"(btl[db][1]), "=r"(btl[db][2]), "=r"(btl[db][3])
                        : "r"(VS + rv * ROWB + (8 + db * 2 + l4) * 16));
                }
#pragma unroll
                for (int db = 0; db < 4; db++)
#pragma unroll
                    for (int nf = 0; nf < 2; nf++) {
                        int nb = db * 2 + nf;
                        asm volatile(
                            "mma.sync.aligned.m16n8k16.row.col.f32.bf16.bf16.f32 "
                            "{%0,%1,%2,%3}, {%4,%5,%6,%7}, {%8,%9}, {%0,%1,%2,%3};"
                            : "+f"(po[nb][0]), "+f"(po[nb][1]), "+f"(po[nb][2]), "+f"(po[nb][3])
                            : "r"(af_hi[0]), "r"(af_hi[1]), "r"(af_hi[2]), "r"(af_hi[3]),
                              "r"(bth[db][nf * 2]), "r"(bth[db][nf * 2 + 1]));
                        asm volatile(
                            "mma.sync.aligned.m16n8k16.row.col.f32.bf16.bf16.f32 "
                            "{%0,%1,%2,%3}, {%4,%5,%6,%7}, {%8,%9}, {%0,%1,%2,%3};"
                            : "+f"(po[nb][0]), "+f"(po[nb][1]), "+f"(po[nb][2]), "+f"(po[nb][3])
                            : "r"(af_hi[0]), "r"(af_hi[1]), "r"(af_hi[2]), "r"(af_hi[3]),
                              "r"(btl[db][nf * 2]), "r"(btl[db][nf * 2 + 1]));
                        asm volatile(
                            "mma.sync.aligned.m16n8k16.row.col.f32.bf16.bf16.f32 "
                            "{%0,%1,%2,%3}, {%4,%5,%6,%7}, {%8,%9}, {%0,%1,%2,%3};"
                            : "+f"(po[nb][0]), "+f"(po[nb][1]), "+f"(po[nb][2]), "+f"(po[nb][3])
                            : "r"(af_lo[0]), "r"(af_lo[1]), "r"(af_lo[2]), "r"(af_lo[3]),
                              "r"(bth[db][nf * 2]), "r"(bth[db][nf * 2 + 1]));
                    }
            }
            __syncthreads();
        }
    }

    ls0 += __shfl_xor_sync(0xffffffffu, ls0, 1);
    ls0 += __shfl_xor_sync(0xffffffffu, ls0, 2);
    ls1 += __shfl_xor_sync(0xffffffffu, ls1, 1);
    ls1 += __shfl_xor_sync(0xffffffffu, ls1, 2);
    float inv0 = fm0 ? 0.f : 1.0f / ls0;
    float inv1 = fm1 ? 0.f : 1.0f / ls1;

    size_t mr0 = ((size_t)b * 1024 + (i0 + rw + lr)) * (size_t)KROW;
    size_t mr1 = ((size_t)b * 1024 + (i0 + rw + lr + 8)) * (size_t)KROW;
#pragma unroll
    for (int nb = 0; nb < 8; nb++) {
        int d = nb * 8 + lc;
        int col = h * 64 + d;
        float x0, x1, y0, y1;
        if (fm0) { x0 = vmean[bh * 64 + d]; x1 = vmean[bh * 64 + d + 1]; }
        else     { x0 = po[nb][0] * inv0;   x1 = po[nb][1] * inv0; }
        if (fm1) { y0 = vmean[bh * 64 + d]; y1 = vmean[bh * 64 + d + 1]; }
        else     { y0 = po[nb][2] * inv1;   y1 = po[nb][3] * inv1; }

        __nv_bfloat16 hx0 = __float2bfloat16(x0), hx1 = __float2bfloat16(x1);
        uint32_t hp0 = (uint32_t)__bfloat16_as_ushort(hx0) | ((uint32_t)__bfloat16_as_ushort(hx1) << 16);
        uint32_t lq0 = pack_bf2(x0 - __bfloat162float(hx0), x1 - __bfloat162float(hx1));
        __nv_bfloat16 hy0 = __float2bfloat16(y0), hy1 = __float2bfloat16(y1);
        uint32_t hp1 = (uint32_t)__bfloat16_as_ushort(hy0) | ((uint32_t)__bfloat16_as_ushort(hy1) << 16);
        uint32_t lq1 = pack_bf2(y0 - __bfloat162float(hy0), y1 - __bfloat162float(hy1));

        *(uint32_t*)(ap + mr0 + col)        = hp0;
        *(uint32_t*)(ap + mr0 + col + 1024) = lq0;
        *(uint32_t*)(ap + mr1 + col)        = hp1;
        *(uint32_t*)(ap + mr1 + col + 1024) = lq1;
    }
}

// ---------------------------------------------------------------------------
extern "C" void kernel_launch(void* const* d_in, const int* in_sizes, int n_in,
                              void* d_out, int out_size)
{
    const float* q   = (const float*)d_in[0];
    const float* k   = (const float*)d_in[1];
    const float* v   = (const float*)d_in[2];
    const int*   pm1 = (const int*)d_in[3];
    const int*   pm2 = (const int*)d_in[4];
    const float* Wq  = (const float*)d_in[5];
    const float* Wk  = (const float*)d_in[6];
    const float* Wv  = (const float*)d_in[7];
    const float* Wo  = (const float*)d_in[8];
    float* out = (float*)d_out;

    __nv_bfloat16 *qs, *ksp, *vsp, *ap, *wp;
    float* vmean;
    cudaGetSymbolAddress((void**)&qs,    g_qs);
    cudaGetSymbolAddress((void**)&ksp,   g_ks);
    cudaGetSymbolAddress((void**)&vsp,   g_vs);
    cudaGetSymbolAddress((void**)&ap,    g_ap);
    cudaGetSymbolAddress((void**)&wp,    g_wp);
    cudaGetSymbolAddress((void**)&vmean, g_vmean);

    cudaFuncSetAttribute(gemm_mma,
        cudaFuncAttributeMaxDynamicSharedMemorySize, GEMM_SMEM);
    cudaFuncSetAttribute(attn_mma,
        cudaFuncAttributeMaxDynamicSharedMemorySize, AT_SMEM);

    // Weight + input conversions (each one launch)
    conv_w_all<<<dim3(512, 4), 256>>>(Wq, Wk, Wv, Wo, wp);
    conv_a3<<<dim3(4096, 3), 256>>>(q, k, v, ap);

    // Merged q/k/v projection GEMMs: grid (4, 64, 3) = 768 CTAs
    gemm_mma<<<dim3(Dc / 256, Mrows / 128, 3), 256, GEMM_SMEM>>>(
        ap, wp, (void*)qs, (void*)ksp, (void*)vsp, 2);

    vmean_kernel<<<Bc * Hc, 256>>>(vsp, vmean);

    // attention writes split A for the final GEMM into ap section 0
    attn_mma<<<dim3(Sc / 128, Bc * Hc), 256, AT_SMEM>>>(qs, ksp, vsp, pm1, pm2, vmean, ap);

    // output projection (section mechanism unused: z=0 reads ap sec0 + needs Wo)
    gemm_mma<<<dim3(Dc / 256, Mrows / 128, 1), 256, GEMM_SMEM>>>(
        ap, wp + 3 * WSEC, (void*)out, (void*)out, (void*)out, 0);
}